// round 9
// baseline (speedup 1.0000x reference)
#include <cuda_runtime.h>
#include <stdint.h>
#include <math.h>

#define NR   512
#define NO   64
#define NT   20
#define NS   300
#define NBUF 400
#define WIN  48
#define DT_F 0.0001f
#define UUB  500.0f

// fallback geometry
#define NCTA  32
#define TPB   512
#define NTH   (NCTA*TPB)
#define KPT   16
// cluster geometry
#define NCTA2 16
#define TPB2  1024
#define NTH2  (NCTA2*TPB2)   // 16384

// cluster smem layout (float units)
#define HIST_F  (2*WIN*NR)
#define SEI_F   HIST_F
#define SEI_B   (SEI_F*4)
#define SMEM_CLF (HIST_F + NR)
#define SMEM_CLB (SMEM_CLF*4)

__device__ float g_wl[NR*NR];
__device__ float g_rsum[NR];
__device__ float g_rssq[NR];
__device__ float g_dgd[NR];
__device__ float g_invnorm;
__device__ float g_pkw[KPT*NTH];   // 262144: fallback 16*16384, cluster 16*16384
__device__ int   g_pko[KPT*NTH];   // fallback 16*16384 byte offs; cluster 8*16384 packed
__device__ float g_lmt[NO*NR];
__device__ float g_Mbuf[2][NR];
__device__ float g_EI[NR];
__device__ int   g_count;

__device__ __forceinline__ int ld_acquire_gpu(const int* p) {
    int v;
    asm volatile("ld.global.acquire.gpu.b32 %0, [%1];" : "=r"(v) : "l"(p) : "memory");
    return v;
}
__device__ __forceinline__ void red_release_gpu(int* p, int v) {
    asm volatile("red.release.gpu.global.add.s32 [%0], %1;" :: "l"(p), "r"(v) : "memory");
}
__device__ __forceinline__ uint32_t smem_u32(const void* p) {
    uint32_t a;
    asm("{ .reg .u64 t; cvta.to.shared.u64 t, %1; cvt.u32.u64 %0, t; }" : "=r"(a) : "l"(p));
    return a;
}
__device__ __forceinline__ uint32_t mapa_u32(uint32_t laddr, uint32_t rank) {
    uint32_t r;
    asm("mapa.shared::cluster.u32 %0, %1, %2;" : "=r"(r) : "r"(laddr), "r"(rank));
    return r;
}
__device__ __forceinline__ void stc_f32(uint32_t raddr, float v) {
    asm volatile("st.shared::cluster.f32 [%0], %1;" :: "r"(raddr), "f"(v) : "memory");
}
#define CLUSTER_ARRIVE() asm volatile("barrier.cluster.arrive.aligned;" ::: "memory")
#define CLUSTER_WAIT()   asm volatile("barrier.cluster.wait.aligned;"   ::: "memory")

// ---------------- P1: w_l + row sums ----------------
__global__ void k_p1(const float* __restrict__ wbb, const float* __restrict__ sc)
{
    int i = blockIdx.x;
    int t = threadIdx.x;
    float a = expf(wbb[i*NR + t]) * sc[i*NR + t];
    float b = expf(wbb[t*NR + i]) * sc[t*NR + i];
    float wl = log1pf(0.5f * (a + b));
    g_wl[i*NR + t] = wl;

    float s1 = wl, s2 = wl * wl;
    #pragma unroll
    for (int off = 16; off; off >>= 1) {
        s1 += __shfl_down_sync(0xffffffffu, s1, off);
        s2 += __shfl_down_sync(0xffffffffu, s2, off);
    }
    __shared__ float sA[16], sB[16];
    int w = t >> 5, l = t & 31;
    if (l == 0) { sA[w] = s1; sB[w] = s2; }
    __syncthreads();
    if (w == 0) {
        float r1 = (l < 16) ? sA[l] : 0.f;
        float r2 = (l < 16) ? sB[l] : 0.f;
        #pragma unroll
        for (int off = 8; off; off >>= 1) {
            r1 += __shfl_down_sync(0xffffffffu, r1, off);
            r2 += __shfl_down_sync(0xffffffffu, r2, off);
        }
        if (l == 0) { g_rsum[i] = r1; g_rssq[i] = r2; }
    }
}

// ---------------- P2m: norm + dg + lm_t + counter reset ----------------
__global__ void k_p2m(const float* __restrict__ lm)
{
    int t = threadIdx.x;
    if (t == 0) g_count = 0;

    float s2 = g_rssq[t];
    #pragma unroll
    for (int off = 16; off; off >>= 1) s2 += __shfl_down_sync(0xffffffffu, s2, off);
    __shared__ float sB[16];
    __shared__ float s_inv;
    int w = t >> 5, l = t & 31;
    if (l == 0) sB[w] = s2;
    __syncthreads();
    if (w == 0) {
        float r2 = (l < 16) ? sB[l] : 0.f;
        #pragma unroll
        for (int off = 8; off; off >>= 1) r2 += __shfl_down_sync(0xffffffffu, r2, off);
        if (l == 0) {
            float inv = 1.0f / sqrtf(r2);
            s_inv = inv;
            g_invnorm = inv;
        }
    }
    __syncthreads();
    g_dgd[t] = -s_inv * g_rsum[t];

    __shared__ float srs[NO];
    if (t < NO) {
        float s = 0.f;
        for (int i = 0; i < NR; i++) s += fabsf(lm[t*NR + i]);
        srs[t] = s;
    }
    __syncthreads();
    float cm = 0.f;
    for (int o = 0; o < NO; o++) cm += lm[o*NR + t] / srs[o];
    cm *= (1.0f / (float)NO);
    for (int o = 0; o < NO; o++) g_lmt[o*NR + t] = lm[o*NR + t] / srs[o] - cm;
}

// ---------------- P3a: fallback packing ----------------
__global__ void k_p3a(const float* __restrict__ dist, const float* __restrict__ theta)
{
    int id = blockIdx.x * TPB + threadIdx.x;
    int k   = id >> 14;
    int gt  = id & 16383;
    int c   = gt >> 9;
    int rem = gt & 511;
    int w2  = rem >> 5;
    int l   = rem & 31;
    int i   = c * 16 + w2;
    int j   = l + (k << 5);

    g_pkw[k*NTH + gt] = g_wl[i*NR + j] * g_invnorm;

    float denom = 1.5f + fmaxf(theta[16], 0.0f);
    int d = (int)(dist[j*NR + i] / denom);
    if (d < 0) d = 0;
    if (d > WIN - 1) d = WIN - 1;
    g_pko[k*NTH + gt] = ((WIN - d) * NR + j) * 4;
}

// ---------------- P3b: cluster packing (1 region/warp, bank=lane) ----------------
// CTA c, warp w owns region i = c*32 + w. Lane l owns sources j = l + 32m, m=0..15.
__global__ void k_p3b(const float* __restrict__ dist, const float* __restrict__ theta)
{
    int gt  = blockIdx.x * 512 + threadIdx.x;    // 0..16383 (32 blocks of 512)
    int c   = gt >> 10;
    int rem = gt & 1023;
    int w2  = rem >> 5;
    int l   = rem & 31;
    int i   = c*32 + w2;
    float denom = 1.5f + fmaxf(theta[16], 0.0f);
    float inv = g_invnorm;

    unsigned offs[16];
    #pragma unroll
    for (int m = 0; m < 16; m++) {
        int j = l + 32*m;
        int d = (int)(dist[j*NR + i] / denom);
        if (d < 0) d = 0;
        if (d > WIN-1) d = WIN-1;
        g_pkw[m*NTH2 + gt] = g_wl[i*NR + j] * inv;
        offs[m] = (unsigned)((WIN - d) * NR + j);
    }
    #pragma unroll
    for (int kk = 0; kk < 8; kk++)
        g_pko[kk*NTH2 + gt] = (int)(offs[2*kk] | (offs[2*kk+1] << 16));
}

__global__ void k_noop() {}

__device__ __forceinline__ void do_eeg(int o, int l, const float* sEI,
                                       float cy0, float y0_, float* out, int wnd)
{
    float sacc = 0.f;
    #pragma unroll
    for (int m2 = 0; m2 < 16; m2++) {
        int i2 = l + 32*m2;
        sacc = fmaf(__ldg(&g_lmt[o*NR + i2]), sEI[i2], sacc);
    }
    #pragma unroll
    for (int off = 16; off; off >>= 1)
        sacc += __shfl_down_sync(0xffffffffu, sacc, off);
    if (l == 0) out[o*NT + wnd] = cy0 * sacc - y0_;
}

// =========================================================================
// CLUSTER kernel: 16 CTAs x 1024 threads, 1 region/warp
// =========================================================================
__global__ void __launch_bounds__(TPB2, 1)
jr_cluster(const float* __restrict__ theta,
           const float* __restrict__ hx,
           const float* __restrict__ hE0,
           const float* __restrict__ ext,
           const float* __restrict__ noise,
           float* __restrict__ out)
{
    extern __shared__ float sm[];
    float* hist = sm;                    // [2*WIN][NR]
    float* sEI  = sm + SEI_F;            // [NR]

    const int tid = threadIdx.x;
    const int c   = blockIdx.x;
    const int w   = tid >> 5;
    const int l   = tid & 31;
    const int gt  = c * TPB2 + tid;

    float wk[16]; unsigned okp[8];
    #pragma unroll
    for (int k = 0; k < 16; k++) wk[k] = g_pkw[k*NTH2 + gt];
    #pragma unroll
    for (int k = 0; k < 8; k++)  okp[k] = (unsigned)g_pko[k*NTH2 + gt];

    // preload history
    for (int idx = tid; idx < WIN*NR; idx += TPB2) {
        int q = idx >> 9;
        int j = idx & 511;
        int cc = (WIN - q) % WIN;
        float v = hE0[j*NBUF + cc];
        hist[q*NR + j]       = v;
        hist[(q+WIN)*NR + j] = v;
    }

    const float A_ = theta[0],  a_ = theta[1],  B_ = theta[2],  b_ = theta[3];
    const float gg = 0.01f + fmaxf(theta[4], 0.f);
    const float gf = 0.01f + fmaxf(theta[5], 0.f);
    const float gb = 0.01f + fmaxf(theta[6], 0.f);
    const float c1 = theta[7],  c2 = theta[8],  c3 = theta[9],  c4 = theta[10];
    const float rstd  = fmaxf(theta[11], 0.f);
    const float ncoef = 150.f + rstd;
    const float vmax = theta[12], v0 = theta[13], r_ = theta[14], y0_ = theta[15];
    const float ku   = (0.5f + fmaxf(theta[17], 0.f)) * theta[18];
    const float cy0  = theta[19];

    const int  i_reg = c*32 + w;          // region owned by this warp (lane 0 leads)
    const bool lead  = (l == 0);

    float M=0,E=0,I=0,Mv=0,Ev=0,Iv=0,dgd_i=0;
    if (lead) {
        M  = hx[i_reg*6 + 0]; E  = hx[i_reg*6 + 1]; I  = hx[i_reg*6 + 2];
        Mv = hx[i_reg*6 + 3]; Ev = hx[i_reg*6 + 4]; Iv = hx[i_reg*6 + 5];
        dgd_i = g_dgd[i_reg];
    }

    // scatter constants: lane l -> peer (l&15); lanes>=16 write the +WIN replica row
    const uint32_t sbase  = smem_u32(sm);
    const uint32_t rbase  = mapa_u32(sbase, (uint32_t)(l & 15));
    const uint32_t kdata  = rbase + ((l >= 16) ? (uint32_t)(WIN*NR*4) : 0u)
                                  + (uint32_t)i_reg * 4u;      // + qq*2048 per step
    const uint32_t rei    = rbase + (uint32_t)SEI_B + (uint32_t)i_reg*4u;  // lanes<16

    __syncthreads();
    CLUSTER_ARRIVE();
    CLUSTER_WAIT();

    // pipelined inputs for step (0,0)
    float u_=0, n0=0, n1=0, n2=0;
    if (lead) {
        n0 = __ldg(noise + i_reg);
        n1 = __ldg(noise + NR + i_reg);
        n2 = __ldg(noise + 2*NR + i_reg);
        u_ = __ldg(ext + i_reg*(NS*NT));
    }

    int qq = 1;
    int pbase = 0;

    CLUSTER_ARRIVE();   // paired by first iteration's WAIT

    for (int wnd = 0; wnd < NT; ++wnd) {
        for (int s = 0; s < NS; ++s) {
            // lead lane: transcendental precompute from OLD state
            float rMb=0, rEb=0, rIb=0, EmI=0, Mn=0, En=0, In=0;
            if (lead) {
                EmI = E - I;
                float S0 = vmax / (1.f + expf(r_ * (v0 - EmI)));
                float S1 = vmax / (1.f + expf(r_ * (v0 - c1*M)));
                float S2 = vmax / (1.f + expf(r_ * (v0 - c3*M)));
                rMb = ku*u_ + rstd*n0 + S0;
                rEb = ncoef*n1 + c2*S1;
                rIb = ncoef*n2 + c4*S2;
                Mn = M + DT_F*Mv;
                En = E + DT_F*Ev;
                In = I + DT_F*Iv;
            }
            // prefetch next step inputs (hidden under wait+gather)
            {
                int sn = s + 1, wn = wnd;
                if (sn == NS) { sn = 0; wn = wnd + 1; if (wn == NT) { wn = NT-1; sn = NS-1; } }
                if (lead) {
                    const float* nb = noise + (size_t)(wn*NS + sn) * 3 * NR + i_reg;
                    n0 = __ldg(nb); n1 = __ldg(nb + NR); n2 = __ldg(nb + 2*NR);
                    u_ = __ldg(ext + i_reg*(NS*NT) + sn*NT + wn);
                }
            }

            CLUSTER_WAIT();   // rows up to n-1 present everywhere

            // EEG of previous window (warps 28..31)
            if (s == 0 && wnd > 0 && w >= 28)
                do_eeg(c*4 + (w - 28), l, sEI, cy0, y0_, out, wnd - 1);

            // ---- gather: 16 terms/lane, conflict-free ----
            const float* hb = hist + pbase;
            float a0 = 0.f, a1 = 0.f;
            #pragma unroll
            for (int kk = 0; kk < 8; kk++) {
                unsigned pk = okp[kk];
                a0 = fmaf(wk[2*kk],   hb[pk & 0xFFFFu], a0);
                a1 = fmaf(wk[2*kk+1], hb[pk >> 16],     a1);
            }
            float acc = a0 + a1;
            #pragma unroll
            for (int off = 16; off; off >>= 1)
                acc += __shfl_xor_sync(0xffffffffu, acc, off);

            // ---- lead lane: finish update ----
            if (lead) {
                float LEd  = acc;
                float lmt_ = LEd + dgd_i * M;
                float let_ = LEd + dgd_i * EmI;
                float rM = rMb + gg*lmt_;
                float rE = rEb + gf*let_;
                float rI = rIb - gb*let_;
                float uM = UUB * tanhf(rM * (1.f/UUB));
                float uE = UUB * tanhf(rE * (1.f/UUB));
                float uI = UUB * tanhf(rI * (1.f/UUB));
                float Mvn = Mv + DT_F*(A_*a_*uM - 2.f*a_*Mv - a_*a_*M);
                float Evn = Ev + DT_F*(A_*a_*uE - 2.f*a_*Ev - a_*a_*E);
                float Ivn = Iv + DT_F*(B_*b_*uI - 2.f*b_*Iv - b_*b_*I);
                M = Mn; E = En; I = In; Mv = Mvn; Ev = Evn; Iv = Ivn;
            }

            // ---- DSMEM scatter: 1 store per lane (both replica rows covered) ----
            float Mval = __shfl_sync(0xffffffffu, M, 0);
            stc_f32(kdata + (uint32_t)(qq*NR)*4u, Mval);
            if (s == NS-1 && l < 16) {
                float EIval = __shfl_sync(0x0000ffffu, E - I, 0);
                stc_f32(rei, EIval);
            }

            CLUSTER_ARRIVE();

            pbase = qq * NR;
            qq++; if (qq == WIN) qq = 0;
        }
    }

    CLUSTER_WAIT();
    if (w >= 28)
        do_eeg(c*4 + (w - 28), l, sEI, cy0, y0_, out, NT - 1);
}

// =========================================================================
// FALLBACK kernel (R2 design, 32 CTAs, L2 counter sync)
// =========================================================================
__global__ void __launch_bounds__(TPB, 1)
jr_main_fb(const float* __restrict__ theta,
           const float* __restrict__ hx,
           const float* __restrict__ hE0,
           const float* __restrict__ ext,
           const float* __restrict__ noise,
           float* __restrict__ out)
{
    extern __shared__ float sm[];
    float* hist  = sm;
    float* s_led = sm + 2*WIN*NR;

    const int tid = threadIdx.x;
    const int c   = blockIdx.x;
    const int w   = tid >> 5;
    const int l   = tid & 31;
    const int gt  = c * TPB + tid;

    float wk[KPT]; int ok[KPT];
    #pragma unroll
    for (int k = 0; k < KPT; k++) {
        wk[k] = g_pkw[k*NTH + gt];
        ok[k] = g_pko[k*NTH + gt];
    }

    for (int idx = tid; idx < WIN*NR; idx += TPB) {
        int q = idx >> 9;
        int j = idx & 511;
        int cc = (WIN - q) % WIN;
        float v = hE0[j*NBUF + cc];
        hist[q*NR + j]       = v;
        hist[(q+WIN)*NR + j] = v;
    }

    const float cy0 = theta[19];
    const float y0_ = theta[15];

    float M=0,E=0,I=0,Mv=0,Ev=0,Iv=0, dgd_i=0;
    float A_=0,a_=0,B_=0,b_=0,gg=0,gf=0,gb=0,c1=0,c2=0,c3=0,c4=0;
    float rstd=0,ncoef=0,vmax=0,v0=0,r_=0,ku=0;
    const int i_reg = c*16 + l;
    if (w == 0) {
        A_ = theta[0];  a_ = theta[1];  B_ = theta[2];  b_ = theta[3];
        gg = 0.01f + fmaxf(theta[4], 0.f);
        gf = 0.01f + fmaxf(theta[5], 0.f);
        gb = 0.01f + fmaxf(theta[6], 0.f);
        c1 = theta[7];  c2 = theta[8];  c3 = theta[9];  c4 = theta[10];
        rstd  = fmaxf(theta[11], 0.f);
        ncoef = 150.f + rstd;
        vmax = theta[12]; v0 = theta[13]; r_ = theta[14];
        ku   = (0.5f + fmaxf(theta[17], 0.f)) * theta[18];
        if (l < 16) {
            M  = hx[i_reg*6 + 0]; E  = hx[i_reg*6 + 1]; I  = hx[i_reg*6 + 2];
            Mv = hx[i_reg*6 + 3]; Ev = hx[i_reg*6 + 4]; Iv = hx[i_reg*6 + 5];
            dgd_i = g_dgd[i_reg];
        }
    }
    __syncthreads();

    int n = 1;
    int pbase = 0;

    for (int wnd = 0; wnd < NT; ++wnd) {
        for (int s = 0; s < NS; ++s) {
            float u_=0, n0=0, n1=0, n2=0;
            if (w == 0 && l < 16) {
                int t_lin = wnd*NS + s;
                const float* nb = noise + (size_t)t_lin * 3 * NR + i_reg;
                n0 = __ldg(nb); n1 = __ldg(nb + NR); n2 = __ldg(nb + 2*NR);
                u_ = __ldg(ext + i_reg*(NS*NT) + s*NT + wnd);
            }

            const char* hrow = (const char*)(hist + pbase);
            float acc0 = 0.f, acc1 = 0.f;
            #pragma unroll
            for (int k = 0; k < KPT; k += 2) {
                acc0 = fmaf(wk[k],   *(const float*)(hrow + ok[k]),   acc0);
                acc1 = fmaf(wk[k+1], *(const float*)(hrow + ok[k+1]), acc1);
            }
            float acc = acc0 + acc1;
            #pragma unroll
            for (int off = 16; off; off >>= 1)
                acc += __shfl_down_sync(0xffffffffu, acc, off);
            if (l == 0) s_led[w] = acc;
            __syncthreads();

            const int par = n & 1;

            if (w == 0) {
                if (l < 16) {
                    float LEd = s_led[l];
                    float EmI = E - I;
                    float S0 = vmax / (1.f + expf(r_ * (v0 - EmI)));
                    float S1 = vmax / (1.f + expf(r_ * (v0 - c1*M)));
                    float S2 = vmax / (1.f + expf(r_ * (v0 - c3*M)));
                    float lmt_ = LEd + dgd_i * M;
                    float let_ = LEd + dgd_i * EmI;
                    float rM = ku*u_ + rstd*n0 + gg*lmt_ + S0;
                    float rE = ncoef*n1 + gf*let_ + c2*S1;
                    float rI = ncoef*n2 - gb*let_ + c4*S2;
                    float Mn = M + DT_F*Mv;
                    float En = E + DT_F*Ev;
                    float In = I + DT_F*Iv;
                    float uM = UUB * tanhf(rM * (1.f/UUB));
                    float uE = UUB * tanhf(rE * (1.f/UUB));
                    float uI = UUB * tanhf(rI * (1.f/UUB));
                    float Mvn = Mv + DT_F*(A_*a_*uM - 2.f*a_*Mv - a_*a_*M);
                    float Evn = Ev + DT_F*(A_*a_*uE - 2.f*a_*Ev - a_*a_*E);
                    float Ivn = Iv + DT_F*(B_*b_*uI - 2.f*b_*Iv - b_*b_*I);
                    M = Mn; E = En; I = In; Mv = Mvn; Ev = Evn; Iv = Ivn;
                    __stcg(&g_Mbuf[par][i_reg], M);
                    if (s == NS-1) __stcg(&g_EI[i_reg], E - I);
                }
                __threadfence();
                if (l == 0) {
                    red_release_gpu(&g_count, 1);
                    const int target = NCTA * n;
                    while (ld_acquire_gpu(&g_count) < target) { }
                }
            }
            __syncthreads();

            {
                float v = __ldcg(&g_Mbuf[par][tid]);
                int q = n % WIN;
                hist[q*NR + tid]       = v;
                hist[(q+WIN)*NR + tid] = v;
            }

            if (s == NS-1 && (w == 8 || w == 9)) {
                int o = 2*c + (w - 8);
                float sacc = 0.f;
                #pragma unroll
                for (int m = 0; m < 16; m++) {
                    int i2 = l + 32*m;
                    sacc = fmaf(__ldg(&g_lmt[o*NR + i2]), __ldcg(&g_EI[i2]), sacc);
                }
                #pragma unroll
                for (int off = 16; off; off >>= 1)
                    sacc += __shfl_down_sync(0xffffffffu, sacc, off);
                if (l == 0) out[o*NT + wnd] = cy0 * sacc - y0_;
            }

            __syncthreads();
            pbase = (n % WIN) * NR;
            n++;
        }
    }
}

extern "C" void kernel_launch(void* const* d_in, const int* in_sizes, int n_in,
                              void* d_out, int out_size)
{
    const float* theta = (const float*)d_in[0];
    const float* lm    = (const float*)d_in[1];
    const float* wbb   = (const float*)d_in[2];
    const float* sc    = (const float*)d_in[3];
    const float* dist  = (const float*)d_in[4];
    const float* hx    = (const float*)d_in[5];
    const float* hE0   = (const float*)d_in[6];
    const float* ext   = (const float*)d_in[7];
    const float* noise = (const float*)d_in[8];
    float* out = (float*)d_out;

    (void)in_sizes; (void)n_in; (void)out_size;

    const size_t SMEM_FB = (size_t)(2*WIN*NR + 32) * sizeof(float);
    const size_t SMEM_CL = (size_t)SMEM_CLB;

    cudaFuncSetAttribute(jr_main_fb, cudaFuncAttributeMaxDynamicSharedMemorySize, (int)SMEM_FB);
    cudaError_t e1 = cudaFuncSetAttribute(jr_cluster, cudaFuncAttributeNonPortableClusterSizeAllowed, 1);
    cudaError_t e2 = cudaFuncSetAttribute(jr_cluster, cudaFuncAttributeMaxDynamicSharedMemorySize, (int)SMEM_CL);

    cudaLaunchConfig_t cfg = {};
    cfg.gridDim  = dim3(NCTA2, 1, 1);
    cfg.blockDim = dim3(TPB2, 1, 1);
    cfg.dynamicSmemBytes = SMEM_CL;
    cfg.stream = 0;
    cudaLaunchAttribute at[1];
    at[0].id = cudaLaunchAttributeClusterDimension;
    at[0].val.clusterDim.x = NCTA2;
    at[0].val.clusterDim.y = 1;
    at[0].val.clusterDim.z = 1;
    cfg.attrs = at;
    cfg.numAttrs = 1;

    int ncl = 0;
    cudaError_t qe = cudaOccupancyMaxActiveClusters(&ncl, jr_cluster, &cfg);
    bool use_cluster = (e1 == cudaSuccess) && (e2 == cudaSuccess) &&
                       (qe == cudaSuccess) && (ncl >= 1);

    k_p1<<<NR, TPB>>>(wbb, sc);
    k_p2m<<<1, TPB>>>(lm);

    if (use_cluster) {
        k_p3b<<<NTH2/512, 512>>>(dist, theta);
        cudaLaunchKernelEx(&cfg, jr_cluster, theta, hx, hE0, ext, noise, out);
    } else {
        k_p3a<<<(KPT*NTH)/TPB, TPB>>>(dist, theta);
        jr_main_fb<<<NCTA, TPB, SMEM_FB>>>(theta, hx, hE0, ext, noise, out);
    }
    k_noop<<<1, 32>>>();
}

// round 10
// speedup vs baseline: 1.3432x; 1.3432x over previous
#include <cuda_runtime.h>
#include <stdint.h>
#include <math.h>

#define NR   512
#define NO   64
#define NT   20
#define NS   300
#define NBUF 400
#define WIN  48
#define DT_F 0.0001f
#define UUB  500.0f

// fallback geometry
#define NCTA  32
#define TPB   512
#define NTH   (NCTA*TPB)
#define KPT   16
// cluster geometry
#define NCTA2 16
#define NTH2  (NCTA2*TPB)   // 8192
#define KPT2  32

// cluster smem layout (float units)
#define HIST_F  (2*WIN*NR)
#define SEI_F   HIST_F
#define SEI_B   (SEI_F*4)
#define MBAR_F  (HIST_F + NR)      // one mbarrier (8 B, aligned)
#define MBAR_B  (MBAR_F*4)
#define SMEM_CLF (MBAR_F + 4)
#define SMEM_CLB (SMEM_CLF*4)

__device__ float g_wl[NR*NR];
__device__ float g_rsum[NR];
__device__ float g_rssq[NR];
__device__ float g_dgd[NR];
__device__ float g_invnorm;
__device__ float g_pkw[KPT*NTH];   // cluster: 32*NTH2 == same size
__device__ int   g_pko[KPT*NTH];   // cluster: 16*NTH2 packed u16 pairs
__device__ float g_lmt[NO*NR];
__device__ float g_Mbuf[2][NR];
__device__ float g_EI[NR];
__device__ int   g_count;

__device__ __forceinline__ int ld_acquire_gpu(const int* p) {
    int v;
    asm volatile("ld.global.acquire.gpu.b32 %0, [%1];" : "=r"(v) : "l"(p) : "memory");
    return v;
}
__device__ __forceinline__ void red_release_gpu(int* p, int v) {
    asm volatile("red.release.gpu.global.add.s32 [%0], %1;" :: "l"(p), "r"(v) : "memory");
}
__device__ __forceinline__ uint32_t smem_u32(const void* p) {
    uint32_t a;
    asm("{ .reg .u64 t; cvta.to.shared.u64 t, %1; cvt.u32.u64 %0, t; }" : "=r"(a) : "l"(p));
    return a;
}
__device__ __forceinline__ uint32_t mapa_u32(uint32_t laddr, uint32_t rank) {
    uint32_t r;
    asm("mapa.shared::cluster.u32 %0, %1, %2;" : "=r"(r) : "r"(laddr), "r"(rank));
    return r;
}
__device__ __forceinline__ void stc_f32(uint32_t raddr, float v) {
    asm volatile("st.shared::cluster.f32 [%0], %1;" :: "r"(raddr), "f"(v) : "memory");
}
__device__ __forceinline__ void fence_cluster() {
    asm volatile("fence.acq_rel.cluster;" ::: "memory");
}
#define CLUSTER_ARRIVE() asm volatile("barrier.cluster.arrive.aligned;" ::: "memory")
#define CLUSTER_WAIT()   asm volatile("barrier.cluster.wait.aligned;"   ::: "memory")

#define MBARRIER_INIT(addr, cnt) \
    asm volatile("mbarrier.init.shared.b64 [%0], %1;" :: "r"(addr), "r"(cnt) : "memory")
// remote release-arrive (cluster scope)
#define MBARRIER_ARRIVE_REMOTE(raddr) \
    asm volatile("mbarrier.arrive.release.cluster.shared::cluster.b64 _, [%0];" :: "r"(raddr) : "memory")
// local wait with cluster-scope acquire
#define MBAR_WAIT_CL(mbar, parity) do { \
    uint32_t _done; \
    asm volatile("{\n\t.reg .pred p;\n\t" \
        "mbarrier.try_wait.parity.acquire.cluster.shared::cta.b64 p, [%1], %2;\n\t" \
        "selp.b32 %0, 1, 0, p;\n\t}" : "=r"(_done) : "r"(mbar), "r"(parity) : "memory"); \
    while (!_done) { \
        asm volatile("{\n\t.reg .pred p;\n\t" \
            "mbarrier.try_wait.parity.acquire.cluster.shared::cta.b64 p, [%1], %2, 0x989680;\n\t" \
            "selp.b32 %0, 1, 0, p;\n\t}" : "=r"(_done) : "r"(mbar), "r"(parity) : "memory"); \
    } \
} while (0)

// ---------------- P1: w_l + row sums ----------------
__global__ void k_p1(const float* __restrict__ wbb, const float* __restrict__ sc)
{
    int i = blockIdx.x;
    int t = threadIdx.x;
    float a = expf(wbb[i*NR + t]) * sc[i*NR + t];
    float b = expf(wbb[t*NR + i]) * sc[t*NR + i];
    float wl = log1pf(0.5f * (a + b));
    g_wl[i*NR + t] = wl;

    float s1 = wl, s2 = wl * wl;
    #pragma unroll
    for (int off = 16; off; off >>= 1) {
        s1 += __shfl_down_sync(0xffffffffu, s1, off);
        s2 += __shfl_down_sync(0xffffffffu, s2, off);
    }
    __shared__ float sA[16], sB[16];
    int w = t >> 5, l = t & 31;
    if (l == 0) { sA[w] = s1; sB[w] = s2; }
    __syncthreads();
    if (w == 0) {
        float r1 = (l < 16) ? sA[l] : 0.f;
        float r2 = (l < 16) ? sB[l] : 0.f;
        #pragma unroll
        for (int off = 8; off; off >>= 1) {
            r1 += __shfl_down_sync(0xffffffffu, r1, off);
            r2 += __shfl_down_sync(0xffffffffu, r2, off);
        }
        if (l == 0) { g_rsum[i] = r1; g_rssq[i] = r2; }
    }
}

// ---------------- P2m: norm + dg + lm_t + counter reset ----------------
__global__ void k_p2m(const float* __restrict__ lm)
{
    int t = threadIdx.x;
    if (t == 0) g_count = 0;

    float s2 = g_rssq[t];
    #pragma unroll
    for (int off = 16; off; off >>= 1) s2 += __shfl_down_sync(0xffffffffu, s2, off);
    __shared__ float sB[16];
    __shared__ float s_inv;
    int w = t >> 5, l = t & 31;
    if (l == 0) sB[w] = s2;
    __syncthreads();
    if (w == 0) {
        float r2 = (l < 16) ? sB[l] : 0.f;
        #pragma unroll
        for (int off = 8; off; off >>= 1) r2 += __shfl_down_sync(0xffffffffu, r2, off);
        if (l == 0) {
            float inv = 1.0f / sqrtf(r2);
            s_inv = inv;
            g_invnorm = inv;
        }
    }
    __syncthreads();
    g_dgd[t] = -s_inv * g_rsum[t];

    __shared__ float srs[NO];
    if (t < NO) {
        float s = 0.f;
        for (int i = 0; i < NR; i++) s += fabsf(lm[t*NR + i]);
        srs[t] = s;
    }
    __syncthreads();
    float cm = 0.f;
    for (int o = 0; o < NO; o++) cm += lm[o*NR + t] / srs[o];
    cm *= (1.0f / (float)NO);
    for (int o = 0; o < NO; o++) g_lmt[o*NR + t] = lm[o*NR + t] / srs[o] - cm;
}

// ---------------- P3a: fallback packing ----------------
__global__ void k_p3a(const float* __restrict__ dist, const float* __restrict__ theta)
{
    int id = blockIdx.x * TPB + threadIdx.x;
    int k   = id >> 14;
    int gt  = id & 16383;
    int c   = gt >> 9;
    int rem = gt & 511;
    int w2  = rem >> 5;
    int l   = rem & 31;
    int i   = c * 16 + w2;
    int j   = l + (k << 5);

    g_pkw[k*NTH + gt] = g_wl[i*NR + j] * g_invnorm;

    float denom = 1.5f + fmaxf(theta[16], 0.0f);
    int d = (int)(dist[j*NR + i] / denom);
    if (d < 0) d = 0;
    if (d > WIN - 1) d = WIN - 1;
    g_pko[k*NTH + gt] = ((WIN - d) * NR + j) * 4;
}

// ---------------- P3b: cluster packing (R5 mapping, packed u16 pairs) ----------------
// lanes 0-15:  region i = c*32+2w,   j = l + 16k
// lanes 16-31: region i = c*32+2w+1, j = (l-16) + 16*((k+1)&31)
__device__ __forceinline__ int jr_src(int l, int k) {
    return (l < 16) ? (l + 16*k) : ((l - 16) + 16*((k + 1) & 31));
}
__global__ void k_p3b(const float* __restrict__ dist, const float* __restrict__ theta)
{
    int gt = blockIdx.x * TPB + threadIdx.x;    // NTH2 threads
    int c   = gt >> 9;
    int rem = gt & 511;
    int w2  = rem >> 5;
    int l   = rem & 31;
    int i   = (l < 16) ? (c*32 + 2*w2) : (c*32 + 2*w2 + 1);
    float denom = 1.5f + fmaxf(theta[16], 0.0f);
    float inv = g_invnorm;

    unsigned offs[32];
    for (int k = 0; k < KPT2; k++) {
        int j = jr_src(l, k);
        int d = (int)(dist[j*NR + i] / denom);
        if (d < 0) d = 0;
        if (d > WIN-1) d = WIN-1;
        g_pkw[k*NTH2 + gt] = g_wl[i*NR + j] * inv;
        offs[k] = (unsigned)((WIN - d) * NR + j);
    }
    for (int kk = 0; kk < 16; kk++)
        g_pko[kk*NTH2 + gt] = (int)(offs[2*kk] | (offs[2*kk+1] << 16));
}

__global__ void k_noop() {}

__device__ __forceinline__ void do_eeg(int o, int l, const float* sEI,
                                       float cy0, float y0_, float* out, int wnd)
{
    float sacc = 0.f;
    #pragma unroll
    for (int m2 = 0; m2 < 16; m2++) {
        int i2 = l + 32*m2;
        sacc = fmaf(__ldg(&g_lmt[o*NR + i2]), sEI[i2], sacc);
    }
    #pragma unroll
    for (int off = 16; off; off >>= 1)
        sacc += __shfl_down_sync(0xffffffffu, sacc, off);
    if (l == 0) out[o*NT + wnd] = cy0 * sacc - y0_;
}

// =========================================================================
// CLUSTER kernel: 16 CTAs x 512, R5 compute structure, mbarrier message sync
// =========================================================================
__global__ void __launch_bounds__(TPB, 1)
jr_cluster(const float* __restrict__ theta,
           const float* __restrict__ hx,
           const float* __restrict__ hE0,
           const float* __restrict__ ext,
           const float* __restrict__ noise,
           float* __restrict__ out)
{
    extern __shared__ float sm[];
    float* hist = sm;                    // [2*WIN][NR]
    float* sEI  = sm + SEI_F;            // [NR]

    const int tid = threadIdx.x;
    const int c   = blockIdx.x;
    const int w   = tid >> 5;
    const int l   = tid & 31;
    const int gt  = c * TPB + tid;
    const uint32_t sbase = smem_u32(sm);
    const uint32_t mbL   = sbase + (uint32_t)MBAR_B;

    float wk[KPT2]; unsigned okp[16];
    #pragma unroll
    for (int k = 0; k < KPT2; k++) wk[k] = g_pkw[k*NTH2 + gt];
    #pragma unroll
    for (int k = 0; k < 16; k++)  okp[k] = (unsigned)g_pko[k*NTH2 + gt];

    // preload history
    for (int idx = tid; idx < WIN*NR; idx += TPB) {
        int q = idx >> 9;
        int j = idx & 511;
        int cc = (WIN - q) % WIN;
        float v = hE0[j*NBUF + cc];
        hist[q*NR + j]       = v;
        hist[(q+WIN)*NR + j] = v;
    }
    if (tid == 0) MBARRIER_INIT(mbL, NCTA2);   // 16 arrivals per phase

    const float A_ = theta[0],  a_ = theta[1],  B_ = theta[2],  b_ = theta[3];
    const float gg = 0.01f + fmaxf(theta[4], 0.f);
    const float gf = 0.01f + fmaxf(theta[5], 0.f);
    const float gb = 0.01f + fmaxf(theta[6], 0.f);
    const float c1 = theta[7],  c2 = theta[8],  c3 = theta[9],  c4 = theta[10];
    const float rstd  = fmaxf(theta[11], 0.f);
    const float ncoef = 150.f + rstd;
    const float vmax = theta[12], v0 = theta[13], r_ = theta[14], y0_ = theta[15];
    const float ku   = (0.5f + fmaxf(theta[17], 0.f)) * theta[18];
    const float cy0  = theta[19];

    const int  rA    = c*32 + 2*w;
    const bool lead  = (l == 0) || (l == 16);
    const int  i_reg = rA + (l >= 16 ? 1 : 0);

    float M=0,E=0,I=0,Mv=0,Ev=0,Iv=0,dgd_i=0;
    if (lead) {
        M  = hx[i_reg*6 + 0]; E  = hx[i_reg*6 + 1]; I  = hx[i_reg*6 + 2];
        Mv = hx[i_reg*6 + 3]; Ev = hx[i_reg*6 + 4]; Iv = hx[i_reg*6 + 5];
        dgd_i = g_dgd[i_reg];
    }

    // scatter constants: lane l -> peer (l & 15), region rj
    const int      rj     = rA + (l >= 16 ? 1 : 0);
    const uint32_t rbase  = mapa_u32(sbase, (uint32_t)(l & 15));
    const uint32_t rdata  = rbase + (uint32_t)rj * 4u;
    const uint32_t rei    = rbase + (uint32_t)SEI_B + (uint32_t)rj*4u;
    // warp 0 lanes 0-15: remote mbarrier addresses
    const uint32_t rmb    = mapa_u32(mbL, (uint32_t)(l & 15));

    __syncthreads();
    CLUSTER_ARRIVE();    // mbarriers initialized cluster-wide
    CLUSTER_WAIT();

    // pipelined inputs for step (0,0)
    float u_=0, n0=0, n1=0, n2=0;
    if (lead) {
        n0 = __ldg(noise + i_reg);
        n1 = __ldg(noise + NR + i_reg);
        n2 = __ldg(noise + 2*NR + i_reg);
        u_ = __ldg(ext + i_reg*(NS*NT));
    }

    int qq = 1;
    int pbase = 0;
    int ph = 0;

    for (int wnd = 0; wnd < NT; ++wnd) {
        for (int s = 0; s < NS; ++s) {
            // lead lanes: transcendental precompute from OLD state
            float rMb=0, rEb=0, rIb=0, EmI=0, Mn=0, En=0, In=0;
            if (lead) {
                EmI = E - I;
                float S0 = vmax / (1.f + expf(r_ * (v0 - EmI)));
                float S1 = vmax / (1.f + expf(r_ * (v0 - c1*M)));
                float S2 = vmax / (1.f + expf(r_ * (v0 - c3*M)));
                rMb = ku*u_ + rstd*n0 + S0;
                rEb = ncoef*n1 + c2*S1;
                rIb = ncoef*n2 + c4*S2;
                Mn = M + DT_F*Mv;
                En = E + DT_F*Ev;
                In = I + DT_F*Iv;
            }
            // prefetch next step inputs
            {
                int sn = s + 1, wn = wnd;
                if (sn == NS) { sn = 0; wn = wnd + 1; if (wn == NT) { wn = NT-1; sn = NS-1; } }
                if (lead) {
                    const float* nb = noise + (size_t)(wn*NS + sn) * 3 * NR + i_reg;
                    n0 = __ldg(nb); n1 = __ldg(nb + NR); n2 = __ldg(nb + 2*NR);
                    u_ = __ldg(ext + i_reg*(NS*NT) + sn*NT + wn);
                }
            }

            // ---- gather: 32 terms/lane, conflict-free ----
            const float* hb = hist + pbase;
            float a0 = 0.f, a1 = 0.f;
            #pragma unroll
            for (int kk = 0; kk < 16; kk++) {
                unsigned pk = okp[kk];
                a0 = fmaf(wk[2*kk],   hb[pk & 0xFFFFu], a0);
                a1 = fmaf(wk[2*kk+1], hb[pk >> 16],     a1);
            }
            float acc = a0 + a1;
            #pragma unroll
            for (int off = 8; off; off >>= 1)
                acc += __shfl_down_sync(0xffffffffu, acc, off, 16);

            // ---- lead lanes: finish update ----
            if (lead) {
                float LEd  = acc;
                float lmt_ = LEd + dgd_i * M;
                float let_ = LEd + dgd_i * EmI;
                float rM = rMb + gg*lmt_;
                float rE = rEb + gf*let_;
                float rI = rIb - gb*let_;
                float uM = UUB * tanhf(rM * (1.f/UUB));
                float uE = UUB * tanhf(rE * (1.f/UUB));
                float uI = UUB * tanhf(rI * (1.f/UUB));
                float Mvn = Mv + DT_F*(A_*a_*uM - 2.f*a_*Mv - a_*a_*M);
                float Evn = Ev + DT_F*(A_*a_*uE - 2.f*a_*Ev - a_*a_*E);
                float Ivn = Iv + DT_F*(B_*b_*uI - 2.f*b_*Iv - b_*b_*I);
                M = Mn; E = En; I = In; Mv = Mvn; Ev = Evn; Iv = Ivn;
            }

            // ---- DSMEM scatter of new M (and EI at window end) ----
            float Mval = __shfl_sync(0xffffffffu, M, (l < 16) ? 0 : 16);
            uint32_t row0 = rdata + (uint32_t)(qq*NR)*4u;
            stc_f32(row0, Mval);
            stc_f32(row0 + (uint32_t)(WIN*NR)*4u, Mval);
            if (s == NS-1) {
                float EIval = __shfl_sync(0xffffffffu, E - I, (l < 16) ? 0 : 16);
                stc_f32(rei, EIval);
            }

            // ---- all warps' scatters done -> 16 remote release-arrives ----
            __syncthreads();
            if (w == 0 && l < 16) {
                fence_cluster();
                MBARRIER_ARRIVE_REMOTE(rmb);
            }

            // ---- wait for all 16 CTAs' arrivals (HW sleep, acquire.cluster) ----
            MBAR_WAIT_CL(mbL, ph);
            ph ^= 1;

            // ---- EEG at window end (warps 4..7 -> channels c*4 + (w-4)) ----
            if (s == NS-1 && (w >= 4 && w < 8))
                do_eeg(c*4 + (w - 4), l, sEI, cy0, y0_, out, wnd);

            pbase = qq * NR;
            qq++; if (qq == WIN) qq = 0;
        }
    }

    CLUSTER_ARRIVE();
    CLUSTER_WAIT();
}

// =========================================================================
// FALLBACK kernel (R2 design, 32 CTAs, L2 counter sync)
// =========================================================================
__global__ void __launch_bounds__(TPB, 1)
jr_main_fb(const float* __restrict__ theta,
           const float* __restrict__ hx,
           const float* __restrict__ hE0,
           const float* __restrict__ ext,
           const float* __restrict__ noise,
           float* __restrict__ out)
{
    extern __shared__ float sm[];
    float* hist  = sm;
    float* s_led = sm + 2*WIN*NR;

    const int tid = threadIdx.x;
    const int c   = blockIdx.x;
    const int w   = tid >> 5;
    const int l   = tid & 31;
    const int gt  = c * TPB + tid;

    float wk[KPT]; int ok[KPT];
    #pragma unroll
    for (int k = 0; k < KPT; k++) {
        wk[k] = g_pkw[k*NTH + gt];
        ok[k] = g_pko[k*NTH + gt];
    }

    for (int idx = tid; idx < WIN*NR; idx += TPB) {
        int q = idx >> 9;
        int j = idx & 511;
        int cc = (WIN - q) % WIN;
        float v = hE0[j*NBUF + cc];
        hist[q*NR + j]       = v;
        hist[(q+WIN)*NR + j] = v;
    }

    const float cy0 = theta[19];
    const float y0_ = theta[15];

    float M=0,E=0,I=0,Mv=0,Ev=0,Iv=0, dgd_i=0;
    float A_=0,a_=0,B_=0,b_=0,gg=0,gf=0,gb=0,c1=0,c2=0,c3=0,c4=0;
    float rstd=0,ncoef=0,vmax=0,v0=0,r_=0,ku=0;
    const int i_reg = c*16 + l;
    if (w == 0) {
        A_ = theta[0];  a_ = theta[1];  B_ = theta[2];  b_ = theta[3];
        gg = 0.01f + fmaxf(theta[4], 0.f);
        gf = 0.01f + fmaxf(theta[5], 0.f);
        gb = 0.01f + fmaxf(theta[6], 0.f);
        c1 = theta[7];  c2 = theta[8];  c3 = theta[9];  c4 = theta[10];
        rstd  = fmaxf(theta[11], 0.f);
        ncoef = 150.f + rstd;
        vmax = theta[12]; v0 = theta[13]; r_ = theta[14];
        ku   = (0.5f + fmaxf(theta[17], 0.f)) * theta[18];
        if (l < 16) {
            M  = hx[i_reg*6 + 0]; E  = hx[i_reg*6 + 1]; I  = hx[i_reg*6 + 2];
            Mv = hx[i_reg*6 + 3]; Ev = hx[i_reg*6 + 4]; Iv = hx[i_reg*6 + 5];
            dgd_i = g_dgd[i_reg];
        }
    }
    __syncthreads();

    int n = 1;
    int pbase = 0;

    for (int wnd = 0; wnd < NT; ++wnd) {
        for (int s = 0; s < NS; ++s) {
            float u_=0, n0=0, n1=0, n2=0;
            if (w == 0 && l < 16) {
                int t_lin = wnd*NS + s;
                const float* nb = noise + (size_t)t_lin * 3 * NR + i_reg;
                n0 = __ldg(nb); n1 = __ldg(nb + NR); n2 = __ldg(nb + 2*NR);
                u_ = __ldg(ext + i_reg*(NS*NT) + s*NT + wnd);
            }

            const char* hrow = (const char*)(hist + pbase);
            float acc0 = 0.f, acc1 = 0.f;
            #pragma unroll
            for (int k = 0; k < KPT; k += 2) {
                acc0 = fmaf(wk[k],   *(const float*)(hrow + ok[k]),   acc0);
                acc1 = fmaf(wk[k+1], *(const float*)(hrow + ok[k+1]), acc1);
            }
            float acc = acc0 + acc1;
            #pragma unroll
            for (int off = 16; off; off >>= 1)
                acc += __shfl_down_sync(0xffffffffu, acc, off);
            if (l == 0) s_led[w] = acc;
            __syncthreads();

            const int par = n & 1;

            if (w == 0) {
                if (l < 16) {
                    float LEd = s_led[l];
                    float EmI = E - I;
                    float S0 = vmax / (1.f + expf(r_ * (v0 - EmI)));
                    float S1 = vmax / (1.f + expf(r_ * (v0 - c1*M)));
                    float S2 = vmax / (1.f + expf(r_ * (v0 - c3*M)));
                    float lmt_ = LEd + dgd_i * M;
                    float let_ = LEd + dgd_i * EmI;
                    float rM = ku*u_ + rstd*n0 + gg*lmt_ + S0;
                    float rE = ncoef*n1 + gf*let_ + c2*S1;
                    float rI = ncoef*n2 - gb*let_ + c4*S2;
                    float Mn = M + DT_F*Mv;
                    float En = E + DT_F*Ev;
                    float In = I + DT_F*Iv;
                    float uM = UUB * tanhf(rM * (1.f/UUB));
                    float uE = UUB * tanhf(rE * (1.f/UUB));
                    float uI = UUB * tanhf(rI * (1.f/UUB));
                    float Mvn = Mv + DT_F*(A_*a_*uM - 2.f*a_*Mv - a_*a_*M);
                    float Evn = Ev + DT_F*(A_*a_*uE - 2.f*a_*Ev - a_*a_*E);
                    float Ivn = Iv + DT_F*(B_*b_*uI - 2.f*b_*Iv - b_*b_*I);
                    M = Mn; E = En; I = In; Mv = Mvn; Ev = Evn; Iv = Ivn;
                    __stcg(&g_Mbuf[par][i_reg], M);
                    if (s == NS-1) __stcg(&g_EI[i_reg], E - I);
                }
                __threadfence();
                if (l == 0) {
                    red_release_gpu(&g_count, 1);
                    const int target = NCTA * n;
                    while (ld_acquire_gpu(&g_count) < target) { }
                }
            }
            __syncthreads();

            {
                float v = __ldcg(&g_Mbuf[par][tid]);
                int q = n % WIN;
                hist[q*NR + tid]       = v;
                hist[(q+WIN)*NR + tid] = v;
            }

            if (s == NS-1 && (w == 8 || w == 9)) {
                int o = 2*c + (w - 8);
                float sacc = 0.f;
                #pragma unroll
                for (int m = 0; m < 16; m++) {
                    int i2 = l + 32*m;
                    sacc = fmaf(__ldg(&g_lmt[o*NR + i2]), __ldcg(&g_EI[i2]), sacc);
                }
                #pragma unroll
                for (int off = 16; off; off >>= 1)
                    sacc += __shfl_down_sync(0xffffffffu, sacc, off);
                if (l == 0) out[o*NT + wnd] = cy0 * sacc - y0_;
            }

            __syncthreads();
            pbase = (n % WIN) * NR;
            n++;
        }
    }
}

extern "C" void kernel_launch(void* const* d_in, const int* in_sizes, int n_in,
                              void* d_out, int out_size)
{
    const float* theta = (const float*)d_in[0];
    const float* lm    = (const float*)d_in[1];
    const float* wbb   = (const float*)d_in[2];
    const float* sc    = (const float*)d_in[3];
    const float* dist  = (const float*)d_in[4];
    const float* hx    = (const float*)d_in[5];
    const float* hE0   = (const float*)d_in[6];
    const float* ext   = (const float*)d_in[7];
    const float* noise = (const float*)d_in[8];
    float* out = (float*)d_out;

    (void)in_sizes; (void)n_in; (void)out_size;

    const size_t SMEM_FB = (size_t)(2*WIN*NR + 32) * sizeof(float);
    const size_t SMEM_CL = (size_t)SMEM_CLB;

    cudaFuncSetAttribute(jr_main_fb, cudaFuncAttributeMaxDynamicSharedMemorySize, (int)SMEM_FB);
    cudaError_t e1 = cudaFuncSetAttribute(jr_cluster, cudaFuncAttributeNonPortableClusterSizeAllowed, 1);
    cudaError_t e2 = cudaFuncSetAttribute(jr_cluster, cudaFuncAttributeMaxDynamicSharedMemorySize, (int)SMEM_CL);

    cudaLaunchConfig_t cfg = {};
    cfg.gridDim  = dim3(NCTA2, 1, 1);
    cfg.blockDim = dim3(TPB, 1, 1);
    cfg.dynamicSmemBytes = SMEM_CL;
    cfg.stream = 0;
    cudaLaunchAttribute at[1];
    at[0].id = cudaLaunchAttributeClusterDimension;
    at[0].val.clusterDim.x = NCTA2;
    at[0].val.clusterDim.y = 1;
    at[0].val.clusterDim.z = 1;
    cfg.attrs = at;
    cfg.numAttrs = 1;

    int ncl = 0;
    cudaError_t qe = cudaOccupancyMaxActiveClusters(&ncl, jr_cluster, &cfg);
    bool use_cluster = (e1 == cudaSuccess) && (e2 == cudaSuccess) &&
                       (qe == cudaSuccess) && (ncl >= 1);

    k_p1<<<NR, TPB>>>(wbb, sc);
    k_p2m<<<1, TPB>>>(lm);

    if (use_cluster) {
        k_p3b<<<NCTA2, TPB>>>(dist, theta);
        cudaLaunchKernelEx(&cfg, jr_cluster, theta, hx, hE0, ext, noise, out);
    } else {
        k_p3a<<<(KPT*NTH)/TPB, TPB>>>(dist, theta);
        jr_main_fb<<<NCTA, TPB, SMEM_FB>>>(theta, hx, hE0, ext, noise, out);
    }
    k_noop<<<1, 32>>>();
}

// round 11
// speedup vs baseline: 1.6887x; 1.2572x over previous
#include <cuda_runtime.h>
#include <stdint.h>
#include <math.h>

#define NR   512
#define NO   64
#define NT   20
#define NS   300
#define NBUF 400
#define WIN  48
#define DT_F 0.0001f
#define UUB  500.0f

// fallback geometry
#define NCTA  32
#define TPB   512
#define NTH   (NCTA*TPB)
#define KPT   16
// cluster geometry
#define NCTA2 16
#define NTH2  (NCTA2*TPB)   // 8192
#define KPT2  32

// cluster smem layout (float units)
#define HIST_F  (2*WIN*NR)
#define SEI_F   HIST_F
#define SEI_B   (SEI_F*4)
#define SMEM_CLF (HIST_F + NR)
#define SMEM_CLB (SMEM_CLF*4)

__device__ float g_wl[NR*NR];
__device__ float g_rsum[NR];
__device__ float g_rssq[NR];
__device__ float g_dgd[NR];
__device__ float g_invnorm;
__device__ float g_pkw[KPT*NTH];   // cluster: 32*NTH2 == same size
__device__ int   g_pko[KPT*NTH];   // cluster: 16*NTH2 packed u16 pairs
__device__ float g_lmt[NO*NR];
__device__ float g_Mbuf[2][NR];
__device__ float g_EI[NR];
__device__ int   g_count;

__device__ __forceinline__ int ld_acquire_gpu(const int* p) {
    int v;
    asm volatile("ld.global.acquire.gpu.b32 %0, [%1];" : "=r"(v) : "l"(p) : "memory");
    return v;
}
__device__ __forceinline__ void red_release_gpu(int* p, int v) {
    asm volatile("red.release.gpu.global.add.s32 [%0], %1;" :: "l"(p), "r"(v) : "memory");
}
__device__ __forceinline__ uint32_t smem_u32(const void* p) {
    uint32_t a;
    asm("{ .reg .u64 t; cvta.to.shared.u64 t, %1; cvt.u32.u64 %0, t; }" : "=r"(a) : "l"(p));
    return a;
}
__device__ __forceinline__ uint32_t mapa_u32(uint32_t laddr, uint32_t rank) {
    uint32_t r;
    asm("mapa.shared::cluster.u32 %0, %1, %2;" : "=r"(r) : "r"(laddr), "r"(rank));
    return r;
}
__device__ __forceinline__ void stc_f32(uint32_t raddr, float v) {
    asm volatile("st.shared::cluster.f32 [%0], %1;" :: "r"(raddr), "f"(v) : "memory");
}
#define CLUSTER_ARRIVE() asm volatile("barrier.cluster.arrive.aligned;" ::: "memory")
#define CLUSTER_WAIT()   asm volatile("barrier.cluster.wait.aligned;"   ::: "memory")

// ---------------- P1: w_l + row sums ----------------
__global__ void k_p1(const float* __restrict__ wbb, const float* __restrict__ sc)
{
    int i = blockIdx.x;
    int t = threadIdx.x;
    float a = expf(wbb[i*NR + t]) * sc[i*NR + t];
    float b = expf(wbb[t*NR + i]) * sc[t*NR + i];
    float wl = log1pf(0.5f * (a + b));
    g_wl[i*NR + t] = wl;

    float s1 = wl, s2 = wl * wl;
    #pragma unroll
    for (int off = 16; off; off >>= 1) {
        s1 += __shfl_down_sync(0xffffffffu, s1, off);
        s2 += __shfl_down_sync(0xffffffffu, s2, off);
    }
    __shared__ float sA[16], sB[16];
    int w = t >> 5, l = t & 31;
    if (l == 0) { sA[w] = s1; sB[w] = s2; }
    __syncthreads();
    if (w == 0) {
        float r1 = (l < 16) ? sA[l] : 0.f;
        float r2 = (l < 16) ? sB[l] : 0.f;
        #pragma unroll
        for (int off = 8; off; off >>= 1) {
            r1 += __shfl_down_sync(0xffffffffu, r1, off);
            r2 += __shfl_down_sync(0xffffffffu, r2, off);
        }
        if (l == 0) { g_rsum[i] = r1; g_rssq[i] = r2; }
    }
}

// ---------------- P2m: norm + dg + lm_t + counter reset ----------------
__global__ void k_p2m(const float* __restrict__ lm)
{
    int t = threadIdx.x;
    if (t == 0) g_count = 0;

    float s2 = g_rssq[t];
    #pragma unroll
    for (int off = 16; off; off >>= 1) s2 += __shfl_down_sync(0xffffffffu, s2, off);
    __shared__ float sB[16];
    __shared__ float s_inv;
    int w = t >> 5, l = t & 31;
    if (l == 0) sB[w] = s2;
    __syncthreads();
    if (w == 0) {
        float r2 = (l < 16) ? sB[l] : 0.f;
        #pragma unroll
        for (int off = 8; off; off >>= 1) r2 += __shfl_down_sync(0xffffffffu, r2, off);
        if (l == 0) {
            float inv = 1.0f / sqrtf(r2);
            s_inv = inv;
            g_invnorm = inv;
        }
    }
    __syncthreads();
    g_dgd[t] = -s_inv * g_rsum[t];

    __shared__ float srs[NO];
    if (t < NO) {
        float s = 0.f;
        for (int i = 0; i < NR; i++) s += fabsf(lm[t*NR + i]);
        srs[t] = s;
    }
    __syncthreads();
    float cm = 0.f;
    for (int o = 0; o < NO; o++) cm += lm[o*NR + t] / srs[o];
    cm *= (1.0f / (float)NO);
    for (int o = 0; o < NO; o++) g_lmt[o*NR + t] = lm[o*NR + t] / srs[o] - cm;
}

// ---------------- P3a: fallback packing ----------------
__global__ void k_p3a(const float* __restrict__ dist, const float* __restrict__ theta)
{
    int id = blockIdx.x * TPB + threadIdx.x;
    int k   = id >> 14;
    int gt  = id & 16383;
    int c   = gt >> 9;
    int rem = gt & 511;
    int w2  = rem >> 5;
    int l   = rem & 31;
    int i   = c * 16 + w2;
    int j   = l + (k << 5);

    g_pkw[k*NTH + gt] = g_wl[i*NR + j] * g_invnorm;

    float denom = 1.5f + fmaxf(theta[16], 0.0f);
    int d = (int)(dist[j*NR + i] / denom);
    if (d < 0) d = 0;
    if (d > WIN - 1) d = WIN - 1;
    g_pko[k*NTH + gt] = ((WIN - d) * NR + j) * 4;
}

// ---------------- P3b: cluster packing (R5 mapping, packed u16 pairs) ----------------
// lanes 0-15:  region i = c*32+2w,   j = l + 16k
// lanes 16-31: region i = c*32+2w+1, j = (l-16) + 16*((k+1)&31)
__device__ __forceinline__ int jr_src(int l, int k) {
    return (l < 16) ? (l + 16*k) : ((l - 16) + 16*((k + 1) & 31));
}
__global__ void k_p3b(const float* __restrict__ dist, const float* __restrict__ theta)
{
    int gt = blockIdx.x * TPB + threadIdx.x;    // NTH2 threads
    int c   = gt >> 9;
    int rem = gt & 511;
    int w2  = rem >> 5;
    int l   = rem & 31;
    int i   = (l < 16) ? (c*32 + 2*w2) : (c*32 + 2*w2 + 1);
    float denom = 1.5f + fmaxf(theta[16], 0.0f);
    float inv = g_invnorm;

    unsigned offs[32];
    for (int k = 0; k < KPT2; k++) {
        int j = jr_src(l, k);
        int d = (int)(dist[j*NR + i] / denom);
        if (d < 0) d = 0;
        if (d > WIN-1) d = WIN-1;
        g_pkw[k*NTH2 + gt] = g_wl[i*NR + j] * inv;
        offs[k] = (unsigned)((WIN - d) * NR + j);
    }
    for (int kk = 0; kk < 16; kk++)
        g_pko[kk*NTH2 + gt] = (int)(offs[2*kk] | (offs[2*kk+1] << 16));
}

__global__ void k_noop() {}

__device__ __forceinline__ void do_eeg(int o, int l, const float* sEI,
                                       float cy0, float y0_, float* out, int wnd)
{
    float sacc = 0.f;
    #pragma unroll
    for (int m2 = 0; m2 < 16; m2++) {
        int i2 = l + 32*m2;
        sacc = fmaf(__ldg(&g_lmt[o*NR + i2]), sEI[i2], sacc);
    }
    #pragma unroll
    for (int off = 16; off; off >>= 1)
        sacc += __shfl_down_sync(0xffffffffu, sacc, off);
    if (l == 0) out[o*NT + wnd] = cy0 * sacc - y0_;
}

// =========================================================================
// CLUSTER kernel: 16 CTAs x 512, R5 structure + PIPELINED predicted-M scatter
// (scatter M(s)=M+DT*Mv at START of step s; barrier flight overlaps compute)
// =========================================================================
__global__ void __launch_bounds__(TPB, 1)
jr_cluster(const float* __restrict__ theta,
           const float* __restrict__ hx,
           const float* __restrict__ hE0,
           const float* __restrict__ ext,
           const float* __restrict__ noise,
           float* __restrict__ out)
{
    extern __shared__ float sm[];
    float* hist = sm;                    // [2*WIN][NR]
    float* sEI  = sm + SEI_F;            // [NR]

    const int tid = threadIdx.x;
    const int c   = blockIdx.x;
    const int w   = tid >> 5;
    const int l   = tid & 31;
    const int gt  = c * TPB + tid;
    const uint32_t sbase = smem_u32(sm);

    float wk[KPT2]; unsigned okp[16];
    #pragma unroll
    for (int k = 0; k < KPT2; k++) wk[k] = g_pkw[k*NTH2 + gt];
    #pragma unroll
    for (int k = 0; k < 16; k++)  okp[k] = (unsigned)g_pko[k*NTH2 + gt];

    // preload history
    for (int idx = tid; idx < WIN*NR; idx += TPB) {
        int q = idx >> 9;
        int j = idx & 511;
        int cc = (WIN - q) % WIN;
        float v = hE0[j*NBUF + cc];
        hist[q*NR + j]       = v;
        hist[(q+WIN)*NR + j] = v;
    }

    const float A_ = theta[0],  a_ = theta[1],  B_ = theta[2],  b_ = theta[3];
    const float gg = 0.01f + fmaxf(theta[4], 0.f);
    const float gf = 0.01f + fmaxf(theta[5], 0.f);
    const float gb = 0.01f + fmaxf(theta[6], 0.f);
    const float c1 = theta[7],  c2 = theta[8],  c3 = theta[9],  c4 = theta[10];
    const float rstd  = fmaxf(theta[11], 0.f);
    const float ncoef = 150.f + rstd;
    const float vmax = theta[12], v0 = theta[13], r_ = theta[14], y0_ = theta[15];
    const float ku   = (0.5f + fmaxf(theta[17], 0.f)) * theta[18];
    const float cy0  = theta[19];

    const int  rA    = c*32 + 2*w;
    const bool lead  = (l == 0) || (l == 16);
    const int  i_reg = rA + (l >= 16 ? 1 : 0);

    float M=0,E=0,I=0,Mv=0,Ev=0,Iv=0,dgd_i=0;
    if (lead) {
        M  = hx[i_reg*6 + 0]; E  = hx[i_reg*6 + 1]; I  = hx[i_reg*6 + 2];
        Mv = hx[i_reg*6 + 3]; Ev = hx[i_reg*6 + 4]; Iv = hx[i_reg*6 + 5];
        dgd_i = g_dgd[i_reg];
    }

    // scatter constants: lane l -> peer (l & 15), region rj
    const int      rj     = rA + (l >= 16 ? 1 : 0);
    const uint32_t rbase  = mapa_u32(sbase, (uint32_t)(l & 15));
    const uint32_t rdata  = rbase + (uint32_t)rj * 4u;
    const uint32_t rei    = rbase + (uint32_t)SEI_B + (uint32_t)rj*4u;

    __syncthreads();
    CLUSTER_ARRIVE();      // init sync: preloads done everywhere
    CLUSTER_WAIT();

    // pipelined inputs for step (0,0)
    float u_=0, n0=0, n1=0, n2=0;
    if (lead) {
        n0 = __ldg(noise + i_reg);
        n1 = __ldg(noise + NR + i_reg);
        n2 = __ldg(noise + 2*NR + i_reg);
        u_ = __ldg(ext + i_reg*(NS*NT));
    }

    int qq = 1;
    int pbase = 0;

    CLUSTER_ARRIVE();      // priming arrive b_0 (step 1's gather needs only preloaded rows)

    for (int wnd = 0; wnd < NT; ++wnd) {
        for (int s = 0; s < NS; ++s) {
            CLUSTER_WAIT();   // pairs previous step's arrive; data sent a step ago has landed

            // EEG of previous window (EI arrived during previous iteration)
            if (s == 0 && wnd > 0 && w >= 4 && w < 8)
                do_eeg(c*4 + (w - 4), l, sEI, cy0, y0_, out, wnd - 1);

            // ---- PIPELINED scatter: predicted M(s) = M + DT*Mv (exact) ----
            float Mnext = 0.f, EInext = 0.f;
            if (lead) {
                Mnext = M + DT_F*Mv;
                if (s == NS-1) EInext = (E + DT_F*Ev) - (I + DT_F*Iv);
            }
            {
                float Mval = __shfl_sync(0xffffffffu, Mnext, (l < 16) ? 0 : 16);
                uint32_t row0 = rdata + (uint32_t)(qq*NR)*4u;
                stc_f32(row0, Mval);
                stc_f32(row0 + (uint32_t)(WIN*NR)*4u, Mval);
                if (s == NS-1) {
                    float EIval = __shfl_sync(0xffffffffu, EInext, (l < 16) ? 0 : 16);
                    stc_f32(rei, EIval);
                }
            }
            CLUSTER_ARRIVE();   // release our scatter; flight overlaps the rest of this step

            // lead lanes: transcendental precompute from OLD state
            float rMb=0, rEb=0, rIb=0, EmI=0, Mn=0, En=0, In=0;
            if (lead) {
                EmI = E - I;
                float S0 = vmax / (1.f + expf(r_ * (v0 - EmI)));
                float S1 = vmax / (1.f + expf(r_ * (v0 - c1*M)));
                float S2 = vmax / (1.f + expf(r_ * (v0 - c3*M)));
                rMb = ku*u_ + rstd*n0 + S0;
                rEb = ncoef*n1 + c2*S1;
                rIb = ncoef*n2 + c4*S2;
                Mn = Mnext;
                En = E + DT_F*Ev;
                In = I + DT_F*Iv;
            }
            // prefetch next step inputs
            {
                int sn = s + 1, wn = wnd;
                if (sn == NS) { sn = 0; wn = wnd + 1; if (wn == NT) { wn = NT-1; sn = NS-1; } }
                if (lead) {
                    const float* nb = noise + (size_t)(wn*NS + sn) * 3 * NR + i_reg;
                    n0 = __ldg(nb); n1 = __ldg(nb + NR); n2 = __ldg(nb + 2*NR);
                    u_ = __ldg(ext + i_reg*(NS*NT) + sn*NT + wn);
                }
            }

            // ---- gather: 32 terms/lane, conflict-free ----
            const float* hb = hist + pbase;
            float a0 = 0.f, a1 = 0.f;
            #pragma unroll
            for (int kk = 0; kk < 16; kk++) {
                unsigned pk = okp[kk];
                a0 = fmaf(wk[2*kk],   hb[pk & 0xFFFFu], a0);
                a1 = fmaf(wk[2*kk+1], hb[pk >> 16],     a1);
            }
            float acc = a0 + a1;
            #pragma unroll
            for (int off = 8; off; off >>= 1)
                acc += __shfl_down_sync(0xffffffffu, acc, off, 16);

            // ---- lead lanes: finish update ----
            if (lead) {
                float LEd  = acc;
                float lmt_ = LEd + dgd_i * M;
                float let_ = LEd + dgd_i * EmI;
                float rM = rMb + gg*lmt_;
                float rE = rEb + gf*let_;
                float rI = rIb - gb*let_;
                float uM = UUB * tanhf(rM * (1.f/UUB));
                float uE = UUB * tanhf(rE * (1.f/UUB));
                float uI = UUB * tanhf(rI * (1.f/UUB));
                float Mvn = Mv + DT_F*(A_*a_*uM - 2.f*a_*Mv - a_*a_*M);
                float Evn = Ev + DT_F*(A_*a_*uE - 2.f*a_*Ev - a_*a_*E);
                float Ivn = Iv + DT_F*(B_*b_*uI - 2.f*b_*Iv - b_*b_*I);
                M = Mn; E = En; I = In; Mv = Mvn; Ev = Evn; Iv = Ivn;
            }

            pbase = qq * NR;
            qq++; if (qq == WIN) qq = 0;
        }
    }

    CLUSTER_WAIT();   // pairs final arrive; last window's EI visible
    if (w >= 4 && w < 8)
        do_eeg(c*4 + (w - 4), l, sEI, cy0, y0_, out, NT - 1);
}

// =========================================================================
// FALLBACK kernel (R2 design, 32 CTAs, L2 counter sync)
// =========================================================================
__global__ void __launch_bounds__(TPB, 1)
jr_main_fb(const float* __restrict__ theta,
           const float* __restrict__ hx,
           const float* __restrict__ hE0,
           const float* __restrict__ ext,
           const float* __restrict__ noise,
           float* __restrict__ out)
{
    extern __shared__ float sm[];
    float* hist  = sm;
    float* s_led = sm + 2*WIN*NR;

    const int tid = threadIdx.x;
    const int c   = blockIdx.x;
    const int w   = tid >> 5;
    const int l   = tid & 31;
    const int gt  = c * TPB + tid;

    float wk[KPT]; int ok[KPT];
    #pragma unroll
    for (int k = 0; k < KPT; k++) {
        wk[k] = g_pkw[k*NTH + gt];
        ok[k] = g_pko[k*NTH + gt];
    }

    for (int idx = tid; idx < WIN*NR; idx += TPB) {
        int q = idx >> 9;
        int j = idx & 511;
        int cc = (WIN - q) % WIN;
        float v = hE0[j*NBUF + cc];
        hist[q*NR + j]       = v;
        hist[(q+WIN)*NR + j] = v;
    }

    const float cy0 = theta[19];
    const float y0_ = theta[15];

    float M=0,E=0,I=0,Mv=0,Ev=0,Iv=0, dgd_i=0;
    float A_=0,a_=0,B_=0,b_=0,gg=0,gf=0,gb=0,c1=0,c2=0,c3=0,c4=0;
    float rstd=0,ncoef=0,vmax=0,v0=0,r_=0,ku=0;
    const int i_reg = c*16 + l;
    if (w == 0) {
        A_ = theta[0];  a_ = theta[1];  B_ = theta[2];  b_ = theta[3];
        gg = 0.01f + fmaxf(theta[4], 0.f);
        gf = 0.01f + fmaxf(theta[5], 0.f);
        gb = 0.01f + fmaxf(theta[6], 0.f);
        c1 = theta[7];  c2 = theta[8];  c3 = theta[9];  c4 = theta[10];
        rstd  = fmaxf(theta[11], 0.f);
        ncoef = 150.f + rstd;
        vmax = theta[12]; v0 = theta[13]; r_ = theta[14];
        ku   = (0.5f + fmaxf(theta[17], 0.f)) * theta[18];
        if (l < 16) {
            M  = hx[i_reg*6 + 0]; E  = hx[i_reg*6 + 1]; I  = hx[i_reg*6 + 2];
            Mv = hx[i_reg*6 + 3]; Ev = hx[i_reg*6 + 4]; Iv = hx[i_reg*6 + 5];
            dgd_i = g_dgd[i_reg];
        }
    }
    __syncthreads();

    int n = 1;
    int pbase = 0;

    for (int wnd = 0; wnd < NT; ++wnd) {
        for (int s = 0; s < NS; ++s) {
            float u_=0, n0=0, n1=0, n2=0;
            if (w == 0 && l < 16) {
                int t_lin = wnd*NS + s;
                const float* nb = noise + (size_t)t_lin * 3 * NR + i_reg;
                n0 = __ldg(nb); n1 = __ldg(nb + NR); n2 = __ldg(nb + 2*NR);
                u_ = __ldg(ext + i_reg*(NS*NT) + s*NT + wnd);
            }

            const char* hrow = (const char*)(hist + pbase);
            float acc0 = 0.f, acc1 = 0.f;
            #pragma unroll
            for (int k = 0; k < KPT; k += 2) {
                acc0 = fmaf(wk[k],   *(const float*)(hrow + ok[k]),   acc0);
                acc1 = fmaf(wk[k+1], *(const float*)(hrow + ok[k+1]), acc1);
            }
            float acc = acc0 + acc1;
            #pragma unroll
            for (int off = 16; off; off >>= 1)
                acc += __shfl_down_sync(0xffffffffu, acc, off);
            if (l == 0) s_led[w] = acc;
            __syncthreads();

            const int par = n & 1;

            if (w == 0) {
                if (l < 16) {
                    float LEd = s_led[l];
                    float EmI = E - I;
                    float S0 = vmax / (1.f + expf(r_ * (v0 - EmI)));
                    float S1 = vmax / (1.f + expf(r_ * (v0 - c1*M)));
                    float S2 = vmax / (1.f + expf(r_ * (v0 - c3*M)));
                    float lmt_ = LEd + dgd_i * M;
                    float let_ = LEd + dgd_i * EmI;
                    float rM = ku*u_ + rstd*n0 + gg*lmt_ + S0;
                    float rE = ncoef*n1 + gf*let_ + c2*S1;
                    float rI = ncoef*n2 - gb*let_ + c4*S2;
                    float Mn = M + DT_F*Mv;
                    float En = E + DT_F*Ev;
                    float In = I + DT_F*Iv;
                    float uM = UUB * tanhf(rM * (1.f/UUB));
                    float uE = UUB * tanhf(rE * (1.f/UUB));
                    float uI = UUB * tanhf(rI * (1.f/UUB));
                    float Mvn = Mv + DT_F*(A_*a_*uM - 2.f*a_*Mv - a_*a_*M);
                    float Evn = Ev + DT_F*(A_*a_*uE - 2.f*a_*Ev - a_*a_*E);
                    float Ivn = Iv + DT_F*(B_*b_*uI - 2.f*b_*Iv - b_*b_*I);
                    M = Mn; E = En; I = In; Mv = Mvn; Ev = Evn; Iv = Ivn;
                    __stcg(&g_Mbuf[par][i_reg], M);
                    if (s == NS-1) __stcg(&g_EI[i_reg], E - I);
                }
                __threadfence();
                if (l == 0) {
                    red_release_gpu(&g_count, 1);
                    const int target = NCTA * n;
                    while (ld_acquire_gpu(&g_count) < target) { }
                }
            }
            __syncthreads();

            {
                float v = __ldcg(&g_Mbuf[par][tid]);
                int q = n % WIN;
                hist[q*NR + tid]       = v;
                hist[(q+WIN)*NR + tid] = v;
            }

            if (s == NS-1 && (w == 8 || w == 9)) {
                int o = 2*c + (w - 8);
                float sacc = 0.f;
                #pragma unroll
                for (int m = 0; m < 16; m++) {
                    int i2 = l + 32*m;
                    sacc = fmaf(__ldg(&g_lmt[o*NR + i2]), __ldcg(&g_EI[i2]), sacc);
                }
                #pragma unroll
                for (int off = 16; off; off >>= 1)
                    sacc += __shfl_down_sync(0xffffffffu, sacc, off);
                if (l == 0) out[o*NT + wnd] = cy0 * sacc - y0_;
            }

            __syncthreads();
            pbase = (n % WIN) * NR;
            n++;
        }
    }
}

extern "C" void kernel_launch(void* const* d_in, const int* in_sizes, int n_in,
                              void* d_out, int out_size)
{
    const float* theta = (const float*)d_in[0];
    const float* lm    = (const float*)d_in[1];
    const float* wbb   = (const float*)d_in[2];
    const float* sc    = (const float*)d_in[3];
    const float* dist  = (const float*)d_in[4];
    const float* hx    = (const float*)d_in[5];
    const float* hE0   = (const float*)d_in[6];
    const float* ext   = (const float*)d_in[7];
    const float* noise = (const float*)d_in[8];
    float* out = (float*)d_out;

    (void)in_sizes; (void)n_in; (void)out_size;

    const size_t SMEM_FB = (size_t)(2*WIN*NR + 32) * sizeof(float);
    const size_t SMEM_CL = (size_t)SMEM_CLB;

    cudaFuncSetAttribute(jr_main_fb, cudaFuncAttributeMaxDynamicSharedMemorySize, (int)SMEM_FB);
    cudaError_t e1 = cudaFuncSetAttribute(jr_cluster, cudaFuncAttributeNonPortableClusterSizeAllowed, 1);
    cudaError_t e2 = cudaFuncSetAttribute(jr_cluster, cudaFuncAttributeMaxDynamicSharedMemorySize, (int)SMEM_CL);

    cudaLaunchConfig_t cfg = {};
    cfg.gridDim  = dim3(NCTA2, 1, 1);
    cfg.blockDim = dim3(TPB, 1, 1);
    cfg.dynamicSmemBytes = SMEM_CL;
    cfg.stream = 0;
    cudaLaunchAttribute at[1];
    at[0].id = cudaLaunchAttributeClusterDimension;
    at[0].val.clusterDim.x = NCTA2;
    at[0].val.clusterDim.y = 1;
    at[0].val.clusterDim.z = 1;
    cfg.attrs = at;
    cfg.numAttrs = 1;

    int ncl = 0;
    cudaError_t qe = cudaOccupancyMaxActiveClusters(&ncl, jr_cluster, &cfg);
    bool use_cluster = (e1 == cudaSuccess) && (e2 == cudaSuccess) &&
                       (qe == cudaSuccess) && (ncl >= 1);

    k_p1<<<NR, TPB>>>(wbb, sc);
    k_p2m<<<1, TPB>>>(lm);

    if (use_cluster) {
        k_p3b<<<NCTA2, TPB>>>(dist, theta);
        cudaLaunchKernelEx(&cfg, jr_cluster, theta, hx, hE0, ext, noise, out);
    } else {
        k_p3a<<<(KPT*NTH)/TPB, TPB>>>(dist, theta);
        jr_main_fb<<<NCTA, TPB, SMEM_FB>>>(theta, hx, hE0, ext, noise, out);
    }
    k_noop<<<1, 32>>>();
}

// round 12
// speedup vs baseline: 1.9450x; 1.1518x over previous
#include <cuda_runtime.h>
#include <stdint.h>
#include <math.h>

#define NR   512
#define NO   64
#define NT   20
#define NS   300
#define NBUF 400
#define WIN  48
#define DT_F 0.0001f
#define UUB  500.0f

// fallback geometry
#define NCTA  32
#define TPB   512
#define NTH   (NCTA*TPB)
#define KPT   16
// cluster geometry
#define NCTA2 16
#define TPB2C 544            // 16 gather warps + 1 updater warp
#define NTH2  (NCTA2*512)    // gather-table threads (warps 0-15 only)
#define KPT2  32

// cluster smem layout (float units)
#define HIST_F  (2*WIN*NR)
#define SEI_F   HIST_F
#define SEI_B   (SEI_F*4)
#define SLED_F  (HIST_F + NR)        // sLEd[2][32] parity-buffered
#define SMEM_CLF (SLED_F + 64)
#define SMEM_CLB (SMEM_CLF*4)

__device__ float g_wl[NR*NR];
__device__ float g_rsum[NR];
__device__ float g_rssq[NR];
__device__ float g_dgd[NR];
__device__ float g_invnorm;
__device__ float g_pkw[KPT*NTH];   // cluster: 32*NTH2 == same size
__device__ int   g_pko[KPT*NTH];   // cluster: 16*NTH2 packed u16 pairs
__device__ float g_lmt[NO*NR];
__device__ float g_Mbuf[2][NR];
__device__ float g_EI[NR];
__device__ int   g_count;

__device__ __forceinline__ int ld_acquire_gpu(const int* p) {
    int v;
    asm volatile("ld.global.acquire.gpu.b32 %0, [%1];" : "=r"(v) : "l"(p) : "memory");
    return v;
}
__device__ __forceinline__ void red_release_gpu(int* p, int v) {
    asm volatile("red.release.gpu.global.add.s32 [%0], %1;" :: "l"(p), "r"(v) : "memory");
}
__device__ __forceinline__ uint32_t smem_u32(const void* p) {
    uint32_t a;
    asm("{ .reg .u64 t; cvta.to.shared.u64 t, %1; cvt.u32.u64 %0, t; }" : "=r"(a) : "l"(p));
    return a;
}
__device__ __forceinline__ uint32_t mapa_u32(uint32_t laddr, uint32_t rank) {
    uint32_t r;
    asm("mapa.shared::cluster.u32 %0, %1, %2;" : "=r"(r) : "r"(laddr), "r"(rank));
    return r;
}
__device__ __forceinline__ void stc_f32(uint32_t raddr, float v) {
    asm volatile("st.shared::cluster.f32 [%0], %1;" :: "r"(raddr), "f"(v) : "memory");
}
#define CLUSTER_ARRIVE() asm volatile("barrier.cluster.arrive.aligned;" ::: "memory")
#define CLUSTER_WAIT()   asm volatile("barrier.cluster.wait.aligned;"   ::: "memory")

// ---------------- P1: w_l + row sums ----------------
__global__ void k_p1(const float* __restrict__ wbb, const float* __restrict__ sc)
{
    int i = blockIdx.x;
    int t = threadIdx.x;
    float a = expf(wbb[i*NR + t]) * sc[i*NR + t];
    float b = expf(wbb[t*NR + i]) * sc[t*NR + i];
    float wl = log1pf(0.5f * (a + b));
    g_wl[i*NR + t] = wl;

    float s1 = wl, s2 = wl * wl;
    #pragma unroll
    for (int off = 16; off; off >>= 1) {
        s1 += __shfl_down_sync(0xffffffffu, s1, off);
        s2 += __shfl_down_sync(0xffffffffu, s2, off);
    }
    __shared__ float sA[16], sB[16];
    int w = t >> 5, l = t & 31;
    if (l == 0) { sA[w] = s1; sB[w] = s2; }
    __syncthreads();
    if (w == 0) {
        float r1 = (l < 16) ? sA[l] : 0.f;
        float r2 = (l < 16) ? sB[l] : 0.f;
        #pragma unroll
        for (int off = 8; off; off >>= 1) {
            r1 += __shfl_down_sync(0xffffffffu, r1, off);
            r2 += __shfl_down_sync(0xffffffffu, r2, off);
        }
        if (l == 0) { g_rsum[i] = r1; g_rssq[i] = r2; }
    }
}

// ---------------- P2m: norm + dg + lm_t + counter reset ----------------
__global__ void k_p2m(const float* __restrict__ lm)
{
    int t = threadIdx.x;
    if (t == 0) g_count = 0;

    float s2 = g_rssq[t];
    #pragma unroll
    for (int off = 16; off; off >>= 1) s2 += __shfl_down_sync(0xffffffffu, s2, off);
    __shared__ float sB[16];
    __shared__ float s_inv;
    int w = t >> 5, l = t & 31;
    if (l == 0) sB[w] = s2;
    __syncthreads();
    if (w == 0) {
        float r2 = (l < 16) ? sB[l] : 0.f;
        #pragma unroll
        for (int off = 8; off; off >>= 1) r2 += __shfl_down_sync(0xffffffffu, r2, off);
        if (l == 0) {
            float inv = 1.0f / sqrtf(r2);
            s_inv = inv;
            g_invnorm = inv;
        }
    }
    __syncthreads();
    g_dgd[t] = -s_inv * g_rsum[t];

    __shared__ float srs[NO];
    if (t < NO) {
        float s = 0.f;
        for (int i = 0; i < NR; i++) s += fabsf(lm[t*NR + i]);
        srs[t] = s;
    }
    __syncthreads();
    float cm = 0.f;
    for (int o = 0; o < NO; o++) cm += lm[o*NR + t] / srs[o];
    cm *= (1.0f / (float)NO);
    for (int o = 0; o < NO; o++) g_lmt[o*NR + t] = lm[o*NR + t] / srs[o] - cm;
}

// ---------------- P3a: fallback packing ----------------
__global__ void k_p3a(const float* __restrict__ dist, const float* __restrict__ theta)
{
    int id = blockIdx.x * TPB + threadIdx.x;
    int k   = id >> 14;
    int gt  = id & 16383;
    int c   = gt >> 9;
    int rem = gt & 511;
    int w2  = rem >> 5;
    int l   = rem & 31;
    int i   = c * 16 + w2;
    int j   = l + (k << 5);

    g_pkw[k*NTH + gt] = g_wl[i*NR + j] * g_invnorm;

    float denom = 1.5f + fmaxf(theta[16], 0.0f);
    int d = (int)(dist[j*NR + i] / denom);
    if (d < 0) d = 0;
    if (d > WIN - 1) d = WIN - 1;
    g_pko[k*NTH + gt] = ((WIN - d) * NR + j) * 4;
}

// ---------------- P3b: cluster packing (R5 mapping, packed u16 pairs) ----------------
// lanes 0-15:  region i = c*32+2w,   j = l + 16k
// lanes 16-31: region i = c*32+2w+1, j = (l-16) + 16*((k+1)&31)
__device__ __forceinline__ int jr_src(int l, int k) {
    return (l < 16) ? (l + 16*k) : ((l - 16) + 16*((k + 1) & 31));
}
__global__ void k_p3b(const float* __restrict__ dist, const float* __restrict__ theta)
{
    int gt = blockIdx.x * TPB + threadIdx.x;    // NTH2 threads (16 blocks x 512)
    int c   = gt >> 9;
    int rem = gt & 511;
    int w2  = rem >> 5;
    int l   = rem & 31;
    int i   = (l < 16) ? (c*32 + 2*w2) : (c*32 + 2*w2 + 1);
    float denom = 1.5f + fmaxf(theta[16], 0.0f);
    float inv = g_invnorm;

    unsigned offs[32];
    for (int k = 0; k < KPT2; k++) {
        int j = jr_src(l, k);
        int d = (int)(dist[j*NR + i] / denom);
        if (d < 0) d = 0;
        if (d > WIN-1) d = WIN-1;
        g_pkw[k*NTH2 + gt] = g_wl[i*NR + j] * inv;
        offs[k] = (unsigned)((WIN - d) * NR + j);
    }
    for (int kk = 0; kk < 16; kk++)
        g_pko[kk*NTH2 + gt] = (int)(offs[2*kk] | (offs[2*kk+1] << 16));
}

__global__ void k_noop() {}

__device__ __forceinline__ void do_eeg(int o, int l, const float* sEI,
                                       float cy0, float y0_, float* out, int wnd)
{
    float sacc = 0.f;
    #pragma unroll
    for (int m2 = 0; m2 < 16; m2++) {
        int i2 = l + 32*m2;
        sacc = fmaf(__ldg(&g_lmt[o*NR + i2]), sEI[i2], sacc);
    }
    #pragma unroll
    for (int off = 16; off; off >>= 1)
        sacc += __shfl_down_sync(0xffffffffu, sacc, off);
    if (l == 0) out[o*NT + wnd] = cy0 * sacc - y0_;
}

// =========================================================================
// CLUSTER kernel: 16 CTAs x 544; warps 0-15 gather, warp 16 = updater
// =========================================================================
__global__ void __launch_bounds__(TPB2C, 1)
jr_cluster(const float* __restrict__ theta,
           const float* __restrict__ hx,
           const float* __restrict__ hE0,
           const float* __restrict__ ext,
           const float* __restrict__ noise,
           float* __restrict__ out)
{
    extern __shared__ float sm[];
    float* hist = sm;                    // [2*WIN][NR]
    float* sEI  = sm + SEI_F;            // [NR]
    float* sLEd = sm + SLED_F;           // [2][32]

    const int tid = threadIdx.x;
    const int c   = blockIdx.x;
    const int w   = tid >> 5;
    const int l   = tid & 31;
    const uint32_t sbase = smem_u32(sm);

    const float A_ = theta[0],  a_ = theta[1],  B_ = theta[2],  b_ = theta[3];
    const float gg = 0.01f + fmaxf(theta[4], 0.f);
    const float gf = 0.01f + fmaxf(theta[5], 0.f);
    const float gb = 0.01f + fmaxf(theta[6], 0.f);
    const float c1 = theta[7],  c2 = theta[8],  c3 = theta[9],  c4 = theta[10];
    const float rstd  = fmaxf(theta[11], 0.f);
    const float ncoef = 150.f + rstd;
    const float vmax = theta[12], v0 = theta[13], r_ = theta[14], y0_ = theta[15];
    const float ku   = (0.5f + fmaxf(theta[17], 0.f)) * theta[18];
    const float cy0  = theta[19];

    // gather warps: coupling tables
    float wk[KPT2]; unsigned okp[16];
    if (w < 16) {
        const int gt = c * 512 + tid;
        #pragma unroll
        for (int k = 0; k < KPT2; k++) wk[k] = g_pkw[k*NTH2 + gt];
        #pragma unroll
        for (int k = 0; k < 16; k++)  okp[k] = (unsigned)g_pko[k*NTH2 + gt];
    }

    // preload history
    for (int idx = tid; idx < WIN*NR; idx += TPB2C) {
        int q = idx >> 9;
        int j = idx & 511;
        int cc = (WIN - q) % WIN;
        float v = hE0[j*NBUF + cc];
        hist[q*NR + j]       = v;
        hist[(q+WIN)*NR + j] = v;
    }

    // updater warp: per-lane region state + scatter bases
    float M=0,E=0,I=0,Mv=0,Ev=0,Iv=0,dgd_i=0;
    float u_=0,n0=0,n1=0,n2=0;
    uint32_t rbl[16];
    const int i_reg = c*32 + l;   // updater's region (warp 16, lane l)
    if (w == 16) {
        M  = hx[i_reg*6 + 0]; E  = hx[i_reg*6 + 1]; I  = hx[i_reg*6 + 2];
        Mv = hx[i_reg*6 + 3]; Ev = hx[i_reg*6 + 4]; Iv = hx[i_reg*6 + 5];
        dgd_i = g_dgd[i_reg];
        #pragma unroll
        for (int k = 0; k < 16; k++)
            rbl[k] = mapa_u32(sbase, (uint32_t)k) + (uint32_t)i_reg * 4u;
        // inputs for (0,0)
        n0 = __ldg(noise + i_reg);
        n1 = __ldg(noise + NR + i_reg);
        n2 = __ldg(noise + 2*NR + i_reg);
        u_ = __ldg(ext + i_reg*(NS*NT));
    }

    __syncthreads();
    CLUSTER_ARRIVE();      // preloads visible everywhere
    CLUSTER_WAIT();
    CLUSTER_ARRIVE();      // priming arrive (first iteration's WAIT)

    int qq = 1;
    int pbase = 0;
    int pp = 0;            // sLEd parity

    for (int wnd = 0; wnd < NT; ++wnd) {
        for (int s = 0; s < NS; ++s) {
            CLUSTER_WAIT();   // all rows <= current-1 present; prev scatters landed

            float uu=0, nn0=0, nn1=0, nn2=0;
            float Mnext = 0.f;

            if (w < 16) {
                // EEG for previous window (EI scattered at (wnd,0), read at (wnd,1))
                if (s == 1 && wnd > 0 && w >= 4 && w < 8)
                    do_eeg(c*4 + (w - 4), l, sEI, cy0, y0_, out, wnd - 1);

                // ---- gather: 32 terms/lane, conflict-free ----
                const float* hb = hist + pbase;
                float a0 = 0.f, a1 = 0.f;
                #pragma unroll
                for (int kk = 0; kk < 16; kk++) {
                    unsigned pk = okp[kk];
                    a0 = fmaf(wk[2*kk],   hb[pk & 0xFFFFu], a0);
                    a1 = fmaf(wk[2*kk+1], hb[pk >> 16],     a1);
                }
                float acc = a0 + a1;
                #pragma unroll
                for (int off = 8; off; off >>= 1)
                    acc += __shfl_down_sync(0xffffffffu, acc, off, 16);
                if (l == 0)  sLEd[pp*32 + 2*w]     = acc;
                if (l == 16) sLEd[pp*32 + 2*w + 1] = acc;
            } else {
                // ---- updater: scatter predicted M (and EI at window starts) ----
                Mnext = M + DT_F*Mv;
                const uint32_t qoff = (uint32_t)(qq*NR)*4u;
                #pragma unroll
                for (int k = 0; k < 16; k++) {
                    uint32_t ad = rbl[k] + qoff;
                    stc_f32(ad, Mnext);
                    stc_f32(ad + (uint32_t)(WIN*NR)*4u, Mnext);
                }
                if (s == 0 && wnd > 0) {
                    float EIv = E - I;   // state = end of previous window
                    #pragma unroll
                    for (int k = 0; k < 16; k++)
                        stc_f32(rbl[k] + (uint32_t)SEI_B, EIv);
                }
                // prefetch next iteration's inputs
                int sn = s + 1, wn = wnd;
                if (sn == NS) { sn = 0; wn = wnd + 1; if (wn == NT) { wn = NT-1; sn = NS-1; } }
                const float* nb = noise + (size_t)(wn*NS + sn) * 3 * NR + i_reg;
                nn0 = __ldg(nb); nn1 = __ldg(nb + NR); nn2 = __ldg(nb + 2*NR);
                uu  = __ldg(ext + i_reg*(NS*NT) + sn*NT + wn);
            }

            __syncthreads();      // LEd published; scatters ordered before arrive
            CLUSTER_ARRIVE();

            if (w == 16) {
                // ---- full ODE update for region i_reg (32 lanes = 32 regions) ----
                float LEd = sLEd[pp*32 + l];
                float EmI = E - I;
                float S0 = vmax / (1.f + expf(r_ * (v0 - EmI)));
                float S1 = vmax / (1.f + expf(r_ * (v0 - c1*M)));
                float S2 = vmax / (1.f + expf(r_ * (v0 - c3*M)));
                float lmt_ = LEd + dgd_i * M;
                float let_ = LEd + dgd_i * EmI;
                float rM = ku*u_ + rstd*n0 + gg*lmt_ + S0;
                float rE = ncoef*n1 + gf*let_ + c2*S1;
                float rI = ncoef*n2 - gb*let_ + c4*S2;
                float En = E + DT_F*Ev;
                float In = I + DT_F*Iv;
                float uM = UUB * tanhf(rM * (1.f/UUB));
                float uE = UUB * tanhf(rE * (1.f/UUB));
                float uI = UUB * tanhf(rI * (1.f/UUB));
                float Mvn = Mv + DT_F*(A_*a_*uM - 2.f*a_*Mv - a_*a_*M);
                float Evn = Ev + DT_F*(A_*a_*uE - 2.f*a_*Ev - a_*a_*E);
                float Ivn = Iv + DT_F*(B_*b_*uI - 2.f*b_*Iv - b_*b_*I);
                M = Mnext; E = En; I = In; Mv = Mvn; Ev = Evn; Iv = Ivn;
                u_ = uu; n0 = nn0; n1 = nn1; n2 = nn2;
            }

            pbase = qq * NR;
            qq++; if (qq == WIN) qq = 0;
            pp ^= 1;
        }
    }

    // trailing: final window's EI + EEG
    if (w == 16) {
        float EIv = E - I;
        #pragma unroll
        for (int k = 0; k < 16; k++)
            stc_f32(rbl[k] + (uint32_t)SEI_B, EIv);
    }
    __syncthreads();
    CLUSTER_ARRIVE();
    CLUSTER_WAIT();
    if (w >= 4 && w < 8)
        do_eeg(c*4 + (w - 4), l, sEI, cy0, y0_, out, NT - 1);
}

// =========================================================================
// FALLBACK kernel (R2 design, 32 CTAs, L2 counter sync)
// =========================================================================
__global__ void __launch_bounds__(TPB, 1)
jr_main_fb(const float* __restrict__ theta,
           const float* __restrict__ hx,
           const float* __restrict__ hE0,
           const float* __restrict__ ext,
           const float* __restrict__ noise,
           float* __restrict__ out)
{
    extern __shared__ float sm[];
    float* hist  = sm;
    float* s_led = sm + 2*WIN*NR;

    const int tid = threadIdx.x;
    const int c   = blockIdx.x;
    const int w   = tid >> 5;
    const int l   = tid & 31;
    const int gt  = c * TPB + tid;

    float wk[KPT]; int ok[KPT];
    #pragma unroll
    for (int k = 0; k < KPT; k++) {
        wk[k] = g_pkw[k*NTH + gt];
        ok[k] = g_pko[k*NTH + gt];
    }

    for (int idx = tid; idx < WIN*NR; idx += TPB) {
        int q = idx >> 9;
        int j = idx & 511;
        int cc = (WIN - q) % WIN;
        float v = hE0[j*NBUF + cc];
        hist[q*NR + j]       = v;
        hist[(q+WIN)*NR + j] = v;
    }

    const float cy0 = theta[19];
    const float y0_ = theta[15];

    float M=0,E=0,I=0,Mv=0,Ev=0,Iv=0, dgd_i=0;
    float A_=0,a_=0,B_=0,b_=0,gg=0,gf=0,gb=0,c1=0,c2=0,c3=0,c4=0;
    float rstd=0,ncoef=0,vmax=0,v0=0,r_=0,ku=0;
    const int i_reg = c*16 + l;
    if (w == 0) {
        A_ = theta[0];  a_ = theta[1];  B_ = theta[2];  b_ = theta[3];
        gg = 0.01f + fmaxf(theta[4], 0.f);
        gf = 0.01f + fmaxf(theta[5], 0.f);
        gb = 0.01f + fmaxf(theta[6], 0.f);
        c1 = theta[7];  c2 = theta[8];  c3 = theta[9];  c4 = theta[10];
        rstd  = fmaxf(theta[11], 0.f);
        ncoef = 150.f + rstd;
        vmax = theta[12]; v0 = theta[13]; r_ = theta[14];
        ku   = (0.5f + fmaxf(theta[17], 0.f)) * theta[18];
        if (l < 16) {
            M  = hx[i_reg*6 + 0]; E  = hx[i_reg*6 + 1]; I  = hx[i_reg*6 + 2];
            Mv = hx[i_reg*6 + 3]; Ev = hx[i_reg*6 + 4]; Iv = hx[i_reg*6 + 5];
            dgd_i = g_dgd[i_reg];
        }
    }
    __syncthreads();

    int n = 1;
    int pbase = 0;

    for (int wnd = 0; wnd < NT; ++wnd) {
        for (int s = 0; s < NS; ++s) {
            float u_=0, n0=0, n1=0, n2=0;
            if (w == 0 && l < 16) {
                int t_lin = wnd*NS + s;
                const float* nb = noise + (size_t)t_lin * 3 * NR + i_reg;
                n0 = __ldg(nb); n1 = __ldg(nb + NR); n2 = __ldg(nb + 2*NR);
                u_ = __ldg(ext + i_reg*(NS*NT) + s*NT + wnd);
            }

            const char* hrow = (const char*)(hist + pbase);
            float acc0 = 0.f, acc1 = 0.f;
            #pragma unroll
            for (int k = 0; k < KPT; k += 2) {
                acc0 = fmaf(wk[k],   *(const float*)(hrow + ok[k]),   acc0);
                acc1 = fmaf(wk[k+1], *(const float*)(hrow + ok[k+1]), acc1);
            }
            float acc = acc0 + acc1;
            #pragma unroll
            for (int off = 16; off; off >>= 1)
                acc += __shfl_down_sync(0xffffffffu, acc, off);
            if (l == 0) s_led[w] = acc;
            __syncthreads();

            const int par = n & 1;

            if (w == 0) {
                if (l < 16) {
                    float LEd = s_led[l];
                    float EmI = E - I;
                    float S0 = vmax / (1.f + expf(r_ * (v0 - EmI)));
                    float S1 = vmax / (1.f + expf(r_ * (v0 - c1*M)));
                    float S2 = vmax / (1.f + expf(r_ * (v0 - c3*M)));
                    float lmt_ = LEd + dgd_i * M;
                    float let_ = LEd + dgd_i * EmI;
                    float rM = ku*u_ + rstd*n0 + gg*lmt_ + S0;
                    float rE = ncoef*n1 + gf*let_ + c2*S1;
                    float rI = ncoef*n2 - gb*let_ + c4*S2;
                    float Mn = M + DT_F*Mv;
                    float En = E + DT_F*Ev;
                    float In = I + DT_F*Iv;
                    float uM = UUB * tanhf(rM * (1.f/UUB));
                    float uE = UUB * tanhf(rE * (1.f/UUB));
                    float uI = UUB * tanhf(rI * (1.f/UUB));
                    float Mvn = Mv + DT_F*(A_*a_*uM - 2.f*a_*Mv - a_*a_*M);
                    float Evn = Ev + DT_F*(A_*a_*uE - 2.f*a_*Ev - a_*a_*E);
                    float Ivn = Iv + DT_F*(B_*b_*uI - 2.f*b_*Iv - b_*b_*I);
                    M = Mn; E = En; I = In; Mv = Mvn; Ev = Evn; Iv = Ivn;
                    __stcg(&g_Mbuf[par][i_reg], M);
                    if (s == NS-1) __stcg(&g_EI[i_reg], E - I);
                }
                __threadfence();
                if (l == 0) {
                    red_release_gpu(&g_count, 1);
                    const int target = NCTA * n;
                    while (ld_acquire_gpu(&g_count) < target) { }
                }
            }
            __syncthreads();

            {
                float v = __ldcg(&g_Mbuf[par][tid]);
                int q = n % WIN;
                hist[q*NR + tid]       = v;
                hist[(q+WIN)*NR + tid] = v;
            }

            if (s == NS-1 && (w == 8 || w == 9)) {
                int o = 2*c + (w - 8);
                float sacc = 0.f;
                #pragma unroll
                for (int m = 0; m < 16; m++) {
                    int i2 = l + 32*m;
                    sacc = fmaf(__ldg(&g_lmt[o*NR + i2]), __ldcg(&g_EI[i2]), sacc);
                }
                #pragma unroll
                for (int off = 16; off; off >>= 1)
                    sacc += __shfl_down_sync(0xffffffffu, sacc, off);
                if (l == 0) out[o*NT + wnd] = cy0 * sacc - y0_;
            }

            __syncthreads();
            pbase = (n % WIN) * NR;
            n++;
        }
    }
}

extern "C" void kernel_launch(void* const* d_in, const int* in_sizes, int n_in,
                              void* d_out, int out_size)
{
    const float* theta = (const float*)d_in[0];
    const float* lm    = (const float*)d_in[1];
    const float* wbb   = (const float*)d_in[2];
    const float* sc    = (const float*)d_in[3];
    const float* dist  = (const float*)d_in[4];
    const float* hx    = (const float*)d_in[5];
    const float* hE0   = (const float*)d_in[6];
    const float* ext   = (const float*)d_in[7];
    const float* noise = (const float*)d_in[8];
    float* out = (float*)d_out;

    (void)in_sizes; (void)n_in; (void)out_size;

    const size_t SMEM_FB = (size_t)(2*WIN*NR + 32) * sizeof(float);
    const size_t SMEM_CL = (size_t)SMEM_CLB;

    cudaFuncSetAttribute(jr_main_fb, cudaFuncAttributeMaxDynamicSharedMemorySize, (int)SMEM_FB);
    cudaError_t e1 = cudaFuncSetAttribute(jr_cluster, cudaFuncAttributeNonPortableClusterSizeAllowed, 1);
    cudaError_t e2 = cudaFuncSetAttribute(jr_cluster, cudaFuncAttributeMaxDynamicSharedMemorySize, (int)SMEM_CL);

    cudaLaunchConfig_t cfg = {};
    cfg.gridDim  = dim3(NCTA2, 1, 1);
    cfg.blockDim = dim3(TPB2C, 1, 1);
    cfg.dynamicSmemBytes = SMEM_CL;
    cfg.stream = 0;
    cudaLaunchAttribute at[1];
    at[0].id = cudaLaunchAttributeClusterDimension;
    at[0].val.clusterDim.x = NCTA2;
    at[0].val.clusterDim.y = 1;
    at[0].val.clusterDim.z = 1;
    cfg.attrs = at;
    cfg.numAttrs = 1;

    int ncl = 0;
    cudaError_t qe = cudaOccupancyMaxActiveClusters(&ncl, jr_cluster, &cfg);
    bool use_cluster = (e1 == cudaSuccess) && (e2 == cudaSuccess) &&
                       (qe == cudaSuccess) && (ncl >= 1);

    k_p1<<<NR, TPB>>>(wbb, sc);
    k_p2m<<<1, TPB>>>(lm);

    if (use_cluster) {
        k_p3b<<<NCTA2, TPB>>>(dist, theta);
        cudaLaunchKernelEx(&cfg, jr_cluster, theta, hx, hE0, ext, noise, out);
    } else {
        k_p3a<<<(KPT*NTH)/TPB, TPB>>>(dist, theta);
        jr_main_fb<<<NCTA, TPB, SMEM_FB>>>(theta, hx, hE0, ext, noise, out);
    }
    k_noop<<<1, 32>>>();
}